// round 1
// baseline (speedup 1.0000x reference)
#include <cuda_runtime.h>
#include <math.h>

#define DIMC 1536
#define NHEAD 12
#define HDIM 128
#define SEQ 5400
#define GHW 900
#define GWID 30

// scratch (device globals: no allocations allowed)
__device__ float g_q[SEQ * DIMC];
__device__ float g_k[SEQ * DIMC];
__device__ float g_v[SEQ * DIMC];
__device__ float g_ao[SEQ * DIMC];

// ---------------------------------------------------------------------------
// SGEMM: C[M,N] = A[M,K] @ B[N,K]^T + bias[N]
// 128x128 tile, BK=8, 256 threads, 8x8 microtile.
// ---------------------------------------------------------------------------
__global__ void __launch_bounds__(256) sgemm_bt_bias(
    const float* __restrict__ A, const float* __restrict__ B,
    const float* __restrict__ bias, float* __restrict__ C,
    int M, int N, int K)
{
    __shared__ float As[8][128];
    __shared__ float Bs[8][128];
    const int tid = threadIdx.x;
    const int bm = blockIdx.y * 128;
    const int bn = blockIdx.x * 128;
    const int tx = tid & 15;
    const int ty = tid >> 4;
    const int lrow = tid >> 1;
    const int lseg = (tid & 1) * 4;

    float acc[8][8];
#pragma unroll
    for (int i = 0; i < 8; ++i)
#pragma unroll
        for (int j = 0; j < 8; ++j) acc[i][j] = 0.f;

    for (int k0 = 0; k0 < K; k0 += 8) {
        int gm = bm + lrow;
        float4 va = make_float4(0.f, 0.f, 0.f, 0.f);
        if (gm < M) va = *(const float4*)(A + (size_t)gm * K + k0 + lseg);
        As[lseg + 0][lrow] = va.x; As[lseg + 1][lrow] = va.y;
        As[lseg + 2][lrow] = va.z; As[lseg + 3][lrow] = va.w;
        int gn = bn + lrow;
        float4 vb = make_float4(0.f, 0.f, 0.f, 0.f);
        if (gn < N) vb = *(const float4*)(B + (size_t)gn * K + k0 + lseg);
        Bs[lseg + 0][lrow] = vb.x; Bs[lseg + 1][lrow] = vb.y;
        Bs[lseg + 2][lrow] = vb.z; Bs[lseg + 3][lrow] = vb.w;
        __syncthreads();
#pragma unroll
        for (int kk = 0; kk < 8; ++kk) {
            float a[8], b[8];
            *(float4*)&a[0] = *(const float4*)&As[kk][ty * 8];
            *(float4*)&a[4] = *(const float4*)&As[kk][ty * 8 + 4];
            *(float4*)&b[0] = *(const float4*)&Bs[kk][tx * 8];
            *(float4*)&b[4] = *(const float4*)&Bs[kk][tx * 8 + 4];
#pragma unroll
            for (int i = 0; i < 8; ++i)
#pragma unroll
                for (int j = 0; j < 8; ++j)
                    acc[i][j] = fmaf(a[i], b[j], acc[i][j]);
        }
        __syncthreads();
    }

#pragma unroll
    for (int i = 0; i < 8; ++i) {
        int gm = bm + ty * 8 + i;
        if (gm >= M) continue;
#pragma unroll
        for (int j = 0; j < 8; j += 4) {
            int gn = bn + tx * 8 + j;
            float4 o;
            o.x = acc[i][j + 0] + bias[gn + 0];
            o.y = acc[i][j + 1] + bias[gn + 1];
            o.z = acc[i][j + 2] + bias[gn + 2];
            o.w = acc[i][j + 3] + bias[gn + 3];
            *(float4*)(C + (size_t)gm * N + gn) = o;
        }
    }
}

// ---------------------------------------------------------------------------
// Fused RMSNorm + RoPE, in-place on g_q (blockIdx.y==0) / g_k (==1).
// One block per token row. Table columns: [0,22)=f, [22,43)=h, [43,64)=w.
// ---------------------------------------------------------------------------
__global__ void __launch_bounds__(256) norm_rope_kernel(
    const float* __restrict__ nqw, const float* __restrict__ nkw,
    const float* __restrict__ cosT, const float* __restrict__ sinT)
{
    __shared__ float buf[DIMC];
    __shared__ float red[8];
    const int row = blockIdx.x;
    float* base = blockIdx.y ? g_k : g_q;
    const float* w = blockIdx.y ? nkw : nqw;
    const int tid = threadIdx.x;

    float ss = 0.f;
#pragma unroll
    for (int j = tid; j < DIMC; j += 256) {
        float v = base[(size_t)row * DIMC + j];
        buf[j] = v;
        ss += v * v;
    }
#pragma unroll
    for (int o = 16; o; o >>= 1) ss += __shfl_xor_sync(0xffffffffu, ss, o);
    if ((tid & 31) == 0) red[tid >> 5] = ss;
    __syncthreads();
    float tot = 0.f;
#pragma unroll
    for (int i = 0; i < 8; ++i) tot += red[i];
    const float rms = rsqrtf(tot * (1.0f / DIMC) + 1e-6f);
#pragma unroll
    for (int j = tid; j < DIMC; j += 256) buf[j] = buf[j] * rms * w[j];
    __syncthreads();

    const int f = row / GHW;
    const int rem = row - f * GHW;
    const int h = rem / GWID;
    const int ww = rem - h * GWID;
#pragma unroll
    for (int p = tid; p < DIMC / 2; p += 256) {
        int n = p >> 6;
        int i = p & 63;
        int pos = (i < 22) ? f : (i < 43) ? h : ww;
        float c = cosT[pos * 64 + i];
        float s = sinT[pos * 64 + i];
        int idx = n * HDIM + 2 * i;
        float xr = buf[idx], xi = buf[idx + 1];
        base[(size_t)row * DIMC + idx]     = xr * c - xi * s;
        base[(size_t)row * DIMC + idx + 1] = xr * s + xi * c;
    }
}

// ---------------------------------------------------------------------------
// Flash attention, fp32, online softmax.
// BQ=64 queries/block, BK=64 keys/tile, 128 threads, grid (85, 12 heads).
// K staged transposed [d][k] stride 67 (conflict-free scalar loads),
// V staged row-major [k][d] stride 132 (conflict-free float4 loads).
// ---------------------------------------------------------------------------
#define BQ 64
#define BK 64
#define QSTR 128
#define KTSTR 67
#define VSTR 132
#define SSTR 68
#define KVREGION 8576   // max(128*67, 64*132)

__global__ void __launch_bounds__(128, 2) attn_kernel()
{
    extern __shared__ float sm[];
    float* sQ  = sm;                       // BQ*QSTR = 8192
    float* sKV = sQ + BQ * QSTR;           // 8576
    float* sS  = sKV + KVREGION;           // BQ*SSTR = 4352
    float* sM  = sS + BQ * SSTR;
    float* sL  = sM + BQ;
    float* sF  = sL + BQ;

    const int tid = threadIdx.x;
    const int tx = tid & 15;
    const int ty = tid >> 4;               // 0..7
    const int q0 = blockIdx.x * BQ;
    const int head = blockIdx.y;
    const size_t hoff = (size_t)head * HDIM;
    const float scale = 0.08838834764831845f; // 1/sqrt(128)

    // load Q tile
#pragma unroll
    for (int it = 0; it < 16; ++it) {
        int idx = tid + it * 128;          // 2048 float4
        int r = idx >> 5, d4 = idx & 31;
        float4 v = make_float4(0.f, 0.f, 0.f, 0.f);
        if (q0 + r < SEQ) v = *(const float4*)(g_q + (size_t)(q0 + r) * DIMC + hoff + d4 * 4);
        *(float4*)(sQ + r * QSTR + d4 * 4) = v;
    }
    if (tid < BQ) { sM[tid] = -1e30f; sL[tid] = 0.f; }

    float acc[8][8];
#pragma unroll
    for (int i = 0; i < 8; ++i)
#pragma unroll
        for (int j = 0; j < 8; ++j) acc[i][j] = 0.f;

    __syncthreads();

    const int nkt = (SEQ + BK - 1) / BK;
    for (int kt = 0; kt < nkt; ++kt) {
        const int k0 = kt * BK;

        // ---- load K transposed: sKV[d*67 + k] ----
#pragma unroll
        for (int it = 0; it < 16; ++it) {
            int idx = tid + it * 128;
            int kk = idx >> 5, d4 = idx & 31;
            float4 v = make_float4(0.f, 0.f, 0.f, 0.f);
            if (k0 + kk < SEQ) v = *(const float4*)(g_k + (size_t)(k0 + kk) * DIMC + hoff + d4 * 4);
            int d = d4 * 4;
            sKV[(d + 0) * KTSTR + kk] = v.x;
            sKV[(d + 1) * KTSTR + kk] = v.y;
            sKV[(d + 2) * KTSTR + kk] = v.z;
            sKV[(d + 3) * KTSTR + kk] = v.w;
        }
        __syncthreads();

        // ---- S = Q K^T (8q x 4k microtile; keys = tx + 16j) ----
        float sc[8][4];
#pragma unroll
        for (int i = 0; i < 8; ++i)
#pragma unroll
            for (int j = 0; j < 4; ++j) sc[i][j] = 0.f;

#pragma unroll 8
        for (int d = 0; d < HDIM; ++d) {
            float kv[4], qv[8];
#pragma unroll
            for (int j = 0; j < 4; ++j) kv[j] = sKV[d * KTSTR + tx + 16 * j];
#pragma unroll
            for (int i = 0; i < 8; ++i) qv[i] = sQ[(ty * 8 + i) * QSTR + d];
#pragma unroll
            for (int i = 0; i < 8; ++i)
#pragma unroll
                for (int j = 0; j < 4; ++j)
                    sc[i][j] = fmaf(qv[i], kv[j], sc[i][j]);
        }
#pragma unroll
        for (int i = 0; i < 8; ++i)
#pragma unroll
            for (int j = 0; j < 4; ++j) {
                int kk = tx + 16 * j;
                sS[(ty * 8 + i) * SSTR + kk] =
                    (k0 + kk < SEQ) ? sc[i][j] * scale : -1e30f;
            }
        __syncthreads();

        // ---- online softmax (2 threads per row) ----
        {
            int r = tid >> 1, sub = tid & 1;
            float mx = -1e30f;
#pragma unroll
            for (int c = 0; c < 32; ++c) mx = fmaxf(mx, sS[r * SSTR + sub + 2 * c]);
            mx = fmaxf(mx, __shfl_xor_sync(0xffffffffu, mx, 1));
            float mOld = sM[r];
            float mNew = fmaxf(mOld, mx);
            float fac = __expf(mOld - mNew);
            float sum = 0.f;
#pragma unroll
            for (int c = 0; c < 32; ++c) {
                int o = r * SSTR + sub + 2 * c;
                float p = __expf(sS[o] - mNew);
                sS[o] = p;
                sum += p;
            }
            sum += __shfl_xor_sync(0xffffffffu, sum, 1);
            if (sub == 0) { sM[r] = mNew; sL[r] = sL[r] * fac + sum; sF[r] = fac; }
        }

        // ---- load V row-major: sKV[k*132 + d] (K no longer needed) ----
#pragma unroll
        for (int it = 0; it < 16; ++it) {
            int idx = tid + it * 128;
            int r = idx >> 5, d4 = idx & 31;
            float4 v = make_float4(0.f, 0.f, 0.f, 0.f);
            if (k0 + r < SEQ) v = *(const float4*)(g_v + (size_t)(k0 + r) * DIMC + hoff + d4 * 4);
            *(float4*)(sKV + r * VSTR + d4 * 4) = v;
        }
        __syncthreads();

        // ---- O += P V (8q x 8d microtile) ----
        float fr[8];
#pragma unroll
        for (int i = 0; i < 8; ++i) fr[i] = sF[ty * 8 + i];
#pragma unroll
        for (int i = 0; i < 8; ++i)
#pragma unroll
            for (int j = 0; j < 8; ++j) acc[i][j] *= fr[i];

#pragma unroll 2
        for (int kk = 0; kk < BK; ++kk) {
            float4 v0 = *(const float4*)(sKV + kk * VSTR + tx * 8);
            float4 v1 = *(const float4*)(sKV + kk * VSTR + tx * 8 + 4);
#pragma unroll
            for (int i = 0; i < 8; ++i) {
                float p = sS[(ty * 8 + i) * SSTR + kk];
                acc[i][0] = fmaf(p, v0.x, acc[i][0]);
                acc[i][1] = fmaf(p, v0.y, acc[i][1]);
                acc[i][2] = fmaf(p, v0.z, acc[i][2]);
                acc[i][3] = fmaf(p, v0.w, acc[i][3]);
                acc[i][4] = fmaf(p, v1.x, acc[i][4]);
                acc[i][5] = fmaf(p, v1.y, acc[i][5]);
                acc[i][6] = fmaf(p, v1.z, acc[i][6]);
                acc[i][7] = fmaf(p, v1.w, acc[i][7]);
            }
        }
        __syncthreads();
    }

    // ---- epilogue: divide by l, store ----
#pragma unroll
    for (int i = 0; i < 8; ++i) {
        int q = q0 + ty * 8 + i;
        if (q >= SEQ) continue;
        float inv = 1.f / sL[ty * 8 + i];
        float4 o0, o1;
        o0.x = acc[i][0] * inv; o0.y = acc[i][1] * inv;
        o0.z = acc[i][2] * inv; o0.w = acc[i][3] * inv;
        o1.x = acc[i][4] * inv; o1.y = acc[i][5] * inv;
        o1.z = acc[i][6] * inv; o1.w = acc[i][7] * inv;
        *(float4*)(g_ao + (size_t)q * DIMC + hoff + tx * 8) = o0;
        *(float4*)(g_ao + (size_t)q * DIMC + hoff + tx * 8 + 4) = o1;
    }
}

// ---------------------------------------------------------------------------
extern "C" void kernel_launch(void* const* d_in, const int* in_sizes, int n_in,
                              void* d_out, int out_size)
{
    const float* x    = (const float*)d_in[0];
    const float* q_w  = (const float*)d_in[1];
    const float* q_b  = (const float*)d_in[2];
    const float* k_w  = (const float*)d_in[3];
    const float* k_b  = (const float*)d_in[4];
    const float* v_w  = (const float*)d_in[5];
    const float* v_b  = (const float*)d_in[6];
    const float* o_w  = (const float*)d_in[7];
    const float* o_b  = (const float*)d_in[8];
    const float* nqw  = (const float*)d_in[9];
    const float* nkw  = (const float*)d_in[10];
    const float* cosT = (const float*)d_in[11];
    const float* sinT = (const float*)d_in[12];
    float* out = (float*)d_out;

    float *dq, *dk, *dv, *dao;
    cudaGetSymbolAddress((void**)&dq, g_q);
    cudaGetSymbolAddress((void**)&dk, g_k);
    cudaGetSymbolAddress((void**)&dv, g_v);
    cudaGetSymbolAddress((void**)&dao, g_ao);

    dim3 gGemm(DIMC / 128, (SEQ + 127) / 128);
    sgemm_bt_bias<<<gGemm, 256>>>(x, q_w, q_b, dq, SEQ, DIMC, DIMC);
    sgemm_bt_bias<<<gGemm, 256>>>(x, k_w, k_b, dk, SEQ, DIMC, DIMC);
    sgemm_bt_bias<<<gGemm, 256>>>(x, v_w, v_b, dv, SEQ, DIMC, DIMC);

    norm_rope_kernel<<<dim3(SEQ, 2), 256>>>(nqw, nkw, cosT, sinT);

    const int smem = (BQ * QSTR + KVREGION + BQ * SSTR + 3 * BQ) * 4;
    cudaFuncSetAttribute(attn_kernel,
                         cudaFuncAttributeMaxDynamicSharedMemorySize, smem);
    attn_kernel<<<dim3((SEQ + BQ - 1) / BQ, NHEAD), 128, smem>>>();

    sgemm_bt_bias<<<gGemm, 256>>>(dao, o_w, o_b, out, SEQ, DIMC, DIMC);
}

// round 2
// speedup vs baseline: 2.2786x; 2.2786x over previous
#include <cuda_runtime.h>
#include <math.h>
#include <stdint.h>

#define DIMC 1536
#define NHEAD 12
#define HDIM 128
#define SEQ 5400
#define GHW 900
#define GWID 30

// scratch (device globals: no allocations allowed)
__device__ float g_q[SEQ * DIMC];
__device__ float g_k[SEQ * DIMC];
__device__ float g_v[SEQ * DIMC];
__device__ float g_ao[SEQ * DIMC];

// ---------------------------------------------------------------------------
// helpers
// ---------------------------------------------------------------------------
__device__ __forceinline__ float to_tf32(float x) {
    uint32_t u;
    asm("cvt.rna.tf32.f32 %0, %1;" : "=r"(u) : "f"(x));
    return __uint_as_float(u);
}
__device__ __forceinline__ uint32_t fu(float x) { return __float_as_uint(x); }

__device__ __forceinline__ void mma_tf32(float* c, const uint32_t* a,
                                         uint32_t b0, uint32_t b1) {
    asm volatile(
        "mma.sync.aligned.m16n8k8.row.col.f32.tf32.tf32.f32 "
        "{%0,%1,%2,%3}, {%4,%5,%6,%7}, {%8,%9}, {%0,%1,%2,%3};\n"
        : "+f"(c[0]), "+f"(c[1]), "+f"(c[2]), "+f"(c[3])
        : "r"(a[0]), "r"(a[1]), "r"(a[2]), "r"(a[3]), "r"(b0), "r"(b1));
}

// ---------------------------------------------------------------------------
// TF32 GEMM: C[M,1536] = A[M,1536] @ B[1536,1536]^T + bias
// 128x128x16 tile, 256 threads (8 warps, 2x4), warp tile 64x32.
// Operands rounded to tf32 at smem fill.
// ---------------------------------------------------------------------------
#define GSTR 20

__global__ void __launch_bounds__(256) gemm_tf32(
    const float* __restrict__ A, const float* __restrict__ B,
    const float* __restrict__ bias, float* __restrict__ C, int M)
{
    __shared__ float As[128 * GSTR];
    __shared__ float Bs[128 * GSTR];
    const int tid = threadIdx.x;
    const int lane = tid & 31;
    const int wid = tid >> 5;
    const int gid = lane >> 2;
    const int tig = lane & 3;
    const int wm = wid & 1;          // 0..1
    const int wn = wid >> 1;         // 0..3
    const int bm = blockIdx.y * 128;
    const int bn = blockIdx.x * 128;

    float acc[4][4][4];
#pragma unroll
    for (int mt = 0; mt < 4; ++mt)
#pragma unroll
        for (int nt = 0; nt < 4; ++nt)
#pragma unroll
            for (int i = 0; i < 4; ++i) acc[mt][nt][i] = 0.f;

    for (int k0 = 0; k0 < DIMC; k0 += 16) {
#pragma unroll
        for (int h = 0; h < 2; ++h) {
            int idx = tid + h * 256;       // 0..511
            int r = idx >> 2, c4 = idx & 3;
            float4 va = make_float4(0.f, 0.f, 0.f, 0.f);
            if (bm + r < M)
                va = *(const float4*)(A + (size_t)(bm + r) * DIMC + k0 + c4 * 4);
            va.x = to_tf32(va.x); va.y = to_tf32(va.y);
            va.z = to_tf32(va.z); va.w = to_tf32(va.w);
            *(float4*)(As + r * GSTR + c4 * 4) = va;
            float4 vb = *(const float4*)(B + (size_t)(bn + r) * DIMC + k0 + c4 * 4);
            vb.x = to_tf32(vb.x); vb.y = to_tf32(vb.y);
            vb.z = to_tf32(vb.z); vb.w = to_tf32(vb.w);
            *(float4*)(Bs + r * GSTR + c4 * 4) = vb;
        }
        __syncthreads();
#pragma unroll
        for (int ks = 0; ks < 2; ++ks) {
            uint32_t af[4][4], bf[4][2];
#pragma unroll
            for (int mt = 0; mt < 4; ++mt) {
                int base = (wm * 64 + mt * 16 + gid) * GSTR + tig + ks * 8;
                af[mt][0] = fu(As[base]);
                af[mt][1] = fu(As[base + 8 * GSTR]);
                af[mt][2] = fu(As[base + 4]);
                af[mt][3] = fu(As[base + 8 * GSTR + 4]);
            }
#pragma unroll
            for (int nt = 0; nt < 4; ++nt) {
                int base = (wn * 32 + nt * 8 + gid) * GSTR + tig + ks * 8;
                bf[nt][0] = fu(Bs[base]);
                bf[nt][1] = fu(Bs[base + 4]);
            }
#pragma unroll
            for (int mt = 0; mt < 4; ++mt)
#pragma unroll
                for (int nt = 0; nt < 4; ++nt)
                    mma_tf32(acc[mt][nt], af[mt], bf[nt][0], bf[nt][1]);
        }
        __syncthreads();
    }

#pragma unroll
    for (int mt = 0; mt < 4; ++mt) {
        int r0 = bm + wm * 64 + mt * 16 + gid;
        int r1 = r0 + 8;
#pragma unroll
        for (int nt = 0; nt < 4; ++nt) {
            int col = bn + wn * 32 + nt * 8 + 2 * tig;
            float b0 = bias[col], b1 = bias[col + 1];
            if (r0 < M) {
                float2 o = make_float2(acc[mt][nt][0] + b0, acc[mt][nt][1] + b1);
                *(float2*)(C + (size_t)r0 * DIMC + col) = o;
            }
            if (r1 < M) {
                float2 o = make_float2(acc[mt][nt][2] + b0, acc[mt][nt][3] + b1);
                *(float2*)(C + (size_t)r1 * DIMC + col) = o;
            }
        }
    }
}

// ---------------------------------------------------------------------------
// Fused RMSNorm + RoPE (unchanged from round 1)
// ---------------------------------------------------------------------------
__global__ void __launch_bounds__(256) norm_rope_kernel(
    const float* __restrict__ nqw, const float* __restrict__ nkw,
    const float* __restrict__ cosT, const float* __restrict__ sinT)
{
    __shared__ float buf[DIMC];
    __shared__ float red[8];
    const int row = blockIdx.x;
    float* base = blockIdx.y ? g_k : g_q;
    const float* w = blockIdx.y ? nkw : nqw;
    const int tid = threadIdx.x;

    float ss = 0.f;
#pragma unroll
    for (int j = tid; j < DIMC; j += 256) {
        float v = base[(size_t)row * DIMC + j];
        buf[j] = v;
        ss += v * v;
    }
#pragma unroll
    for (int o = 16; o; o >>= 1) ss += __shfl_xor_sync(0xffffffffu, ss, o);
    if ((tid & 31) == 0) red[tid >> 5] = ss;
    __syncthreads();
    float tot = 0.f;
#pragma unroll
    for (int i = 0; i < 8; ++i) tot += red[i];
    const float rms = rsqrtf(tot * (1.0f / DIMC) + 1e-6f);
#pragma unroll
    for (int j = tid; j < DIMC; j += 256) buf[j] = buf[j] * rms * w[j];
    __syncthreads();

    const int f = row / GHW;
    const int rem = row - f * GHW;
    const int h = rem / GWID;
    const int ww = rem - h * GWID;
#pragma unroll
    for (int p = tid; p < DIMC / 2; p += 256) {
        int n = p >> 6;
        int i = p & 63;
        int pos = (i < 22) ? f : (i < 43) ? h : ww;
        float c = cosT[pos * 64 + i];
        float s = sinT[pos * 64 + i];
        int idx = n * HDIM + 2 * i;
        float xr = buf[idx], xi = buf[idx + 1];
        base[(size_t)row * DIMC + idx]     = xr * c - xi * s;
        base[(size_t)row * DIMC + idx + 1] = xr * s + xi * c;
    }
}

// ---------------------------------------------------------------------------
// Flash attention with TF32 mma. BQ=64, BK=64, 128 threads (4 warps).
// Warp w owns q-rows [w*16, w*16+16). Q fragments register-resident.
// smem: sK [64][132] (Q staging, then K tiles), sVt [128][68] (V^T),
//       sP [64][68].
// ---------------------------------------------------------------------------
#define AQ_STR 132
#define AV_STR 68
#define AP_STR 68
#define ASM_K 0
#define ASM_VT (64 * AQ_STR)                 // 8448
#define ASM_P  (ASM_VT + 128 * AV_STR)       // 8448 + 8704 = 17152
#define ASM_TOT (ASM_P + 64 * AP_STR)        // 21504 floats = 86016 B

__global__ void __launch_bounds__(128) attn_mma()
{
    extern __shared__ float sm[];
    float* sK  = sm + ASM_K;
    float* sVt = sm + ASM_VT;
    float* sP  = sm + ASM_P;

    const int tid = threadIdx.x;
    const int lane = tid & 31;
    const int w = tid >> 5;
    const int gid = lane >> 2;
    const int tig = lane & 3;
    const int w16 = w * 16;
    const int q0 = blockIdx.x * 64;
    const int head = blockIdx.y;
    const size_t hoff = (size_t)head * HDIM;
    const float scale = 0.08838834764831845f;  // 1/sqrt(128), folded into Q

    // ---- stage Q (scaled + tf32-rounded) into sK, then lift to registers ----
#pragma unroll
    for (int it = 0; it < 16; ++it) {
        int idx = tid + it * 128;
        int r = idx >> 5, d4 = idx & 31;
        float4 v = make_float4(0.f, 0.f, 0.f, 0.f);
        if (q0 + r < SEQ)
            v = *(const float4*)(g_q + (size_t)(q0 + r) * DIMC + hoff + d4 * 4);
        v.x = to_tf32(v.x * scale); v.y = to_tf32(v.y * scale);
        v.z = to_tf32(v.z * scale); v.w = to_tf32(v.w * scale);
        *(float4*)(sK + r * AQ_STR + d4 * 4) = v;
    }
    __syncthreads();

    uint32_t qa[16][4];
#pragma unroll
    for (int ks = 0; ks < 16; ++ks) {
        int base = (w16 + gid) * AQ_STR + tig + ks * 8;
        qa[ks][0] = fu(sK[base]);
        qa[ks][1] = fu(sK[base + 8 * AQ_STR]);
        qa[ks][2] = fu(sK[base + 4]);
        qa[ks][3] = fu(sK[base + 8 * AQ_STR + 4]);
    }
    __syncthreads();

    float oacc[16][4];
#pragma unroll
    for (int dt = 0; dt < 16; ++dt)
#pragma unroll
        for (int i = 0; i < 4; ++i) oacc[dt][i] = 0.f;
    float m0 = -1e30f, m1 = -1e30f, l0 = 0.f, l1 = 0.f;

    const int nkt = (SEQ + 63) / 64;
    for (int kt = 0; kt < nkt; ++kt) {
        const int k0 = kt * 64;

        // ---- fill K tile [64][128] stride 132 (tf32) ----
#pragma unroll
        for (int it = 0; it < 16; ++it) {
            int idx = tid + it * 128;
            int r = idx >> 5, d4 = idx & 31;
            float4 v = make_float4(0.f, 0.f, 0.f, 0.f);
            if (k0 + r < SEQ)
                v = *(const float4*)(g_k + (size_t)(k0 + r) * DIMC + hoff + d4 * 4);
            v.x = to_tf32(v.x); v.y = to_tf32(v.y);
            v.z = to_tf32(v.z); v.w = to_tf32(v.w);
            *(float4*)(sK + r * AQ_STR + d4 * 4) = v;
        }
        // ---- fill V^T [128 d][64 k] stride 68 (tf32) ----
        {
            int d = w * 32 + lane;   // 0..127
            const float* vp = g_v + hoff + d;
#pragma unroll
            for (int kk4 = 0; kk4 < 16; ++kk4) {
                float4 vv;
                int kb = k0 + kk4 * 4;
                vv.x = (kb + 0 < SEQ) ? to_tf32(vp[(size_t)(kb + 0) * DIMC]) : 0.f;
                vv.y = (kb + 1 < SEQ) ? to_tf32(vp[(size_t)(kb + 1) * DIMC]) : 0.f;
                vv.z = (kb + 2 < SEQ) ? to_tf32(vp[(size_t)(kb + 2) * DIMC]) : 0.f;
                vv.w = (kb + 3 < SEQ) ? to_tf32(vp[(size_t)(kb + 3) * DIMC]) : 0.f;
                *(float4*)(sVt + d * AV_STR + kk4 * 4) = vv;
            }
        }
        __syncthreads();

        // ---- S = Q K^T via mma ----
        float sacc[8][4];
#pragma unroll
        for (int nt = 0; nt < 8; ++nt)
#pragma unroll
            for (int i = 0; i < 4; ++i) sacc[nt][i] = 0.f;

#pragma unroll
        for (int ks = 0; ks < 16; ++ks) {
#pragma unroll
            for (int nt = 0; nt < 8; ++nt) {
                int base = (nt * 8 + gid) * AQ_STR + tig + ks * 8;
                mma_tf32(sacc[nt], qa[ks], fu(sK[base]), fu(sK[base + 4]));
            }
        }

        // ---- mask tail keys ----
        int krem = SEQ - k0;
        if (krem < 64) {
#pragma unroll
            for (int nt = 0; nt < 8; ++nt) {
                int c = nt * 8 + 2 * tig;
                if (c >= krem)     { sacc[nt][0] = -1e30f; sacc[nt][2] = -1e30f; }
                if (c + 1 >= krem) { sacc[nt][1] = -1e30f; sacc[nt][3] = -1e30f; }
            }
        }

        // ---- online softmax (rows gid / gid+8 within warp's 16 rows) ----
        float mx0 = -1e30f, mx1 = -1e30f;
#pragma unroll
        for (int nt = 0; nt < 8; ++nt) {
            mx0 = fmaxf(mx0, fmaxf(sacc[nt][0], sacc[nt][1]));
            mx1 = fmaxf(mx1, fmaxf(sacc[nt][2], sacc[nt][3]));
        }
        mx0 = fmaxf(mx0, __shfl_xor_sync(0xffffffffu, mx0, 1));
        mx0 = fmaxf(mx0, __shfl_xor_sync(0xffffffffu, mx0, 2));
        mx1 = fmaxf(mx1, __shfl_xor_sync(0xffffffffu, mx1, 1));
        mx1 = fmaxf(mx1, __shfl_xor_sync(0xffffffffu, mx1, 2));

        float m0n = fmaxf(m0, mx0), m1n = fmaxf(m1, mx1);
        float f0 = __expf(m0 - m0n), f1 = __expf(m1 - m1n);
        float s0 = 0.f, s1 = 0.f;
#pragma unroll
        for (int nt = 0; nt < 8; ++nt) {
            float p0 = __expf(sacc[nt][0] - m0n);
            float p1 = __expf(sacc[nt][1] - m0n);
            float p2 = __expf(sacc[nt][2] - m1n);
            float p3 = __expf(sacc[nt][3] - m1n);
            s0 += p0 + p1; s1 += p2 + p3;
            *(float2*)(sP + (w16 + gid) * AP_STR + nt * 8 + 2 * tig) =
                make_float2(to_tf32(p0), to_tf32(p1));
            *(float2*)(sP + (w16 + gid + 8) * AP_STR + nt * 8 + 2 * tig) =
                make_float2(to_tf32(p2), to_tf32(p3));
        }
        s0 += __shfl_xor_sync(0xffffffffu, s0, 1);
        s0 += __shfl_xor_sync(0xffffffffu, s0, 2);
        s1 += __shfl_xor_sync(0xffffffffu, s1, 1);
        s1 += __shfl_xor_sync(0xffffffffu, s1, 2);
        l0 = l0 * f0 + s0;
        l1 = l1 * f1 + s1;
        m0 = m0n; m1 = m1n;
#pragma unroll
        for (int dt = 0; dt < 16; ++dt) {
            oacc[dt][0] *= f0; oacc[dt][1] *= f0;
            oacc[dt][2] *= f1; oacc[dt][3] *= f1;
        }
        __syncwarp();

        // ---- O += P V via mma ----
#pragma unroll
        for (int ks = 0; ks < 8; ++ks) {
            uint32_t pa[4];
            int pb = (w16 + gid) * AP_STR + tig + ks * 8;
            pa[0] = fu(sP[pb]);
            pa[1] = fu(sP[pb + 8 * AP_STR]);
            pa[2] = fu(sP[pb + 4]);
            pa[3] = fu(sP[pb + 8 * AP_STR + 4]);
#pragma unroll
            for (int dt = 0; dt < 16; ++dt) {
                int vb = (dt * 8 + gid) * AV_STR + tig + ks * 8;
                mma_tf32(oacc[dt], pa, fu(sVt[vb]), fu(sVt[vb + 4]));
            }
        }
        __syncthreads();
    }

    // ---- epilogue ----
    float inv0 = 1.f / l0, inv1 = 1.f / l1;
    int r0 = q0 + w16 + gid;
    int r1 = r0 + 8;
#pragma unroll
    for (int dt = 0; dt < 16; ++dt) {
        int col = dt * 8 + 2 * tig;
        if (r0 < SEQ)
            *(float2*)(g_ao + (size_t)r0 * DIMC + hoff + col) =
                make_float2(oacc[dt][0] * inv0, oacc[dt][1] * inv0);
        if (r1 < SEQ)
            *(float2*)(g_ao + (size_t)r1 * DIMC + hoff + col) =
                make_float2(oacc[dt][2] * inv1, oacc[dt][3] * inv1);
    }
}

// ---------------------------------------------------------------------------
extern "C" void kernel_launch(void* const* d_in, const int* in_sizes, int n_in,
                              void* d_out, int out_size)
{
    const float* x    = (const float*)d_in[0];
    const float* q_w  = (const float*)d_in[1];
    const float* q_b  = (const float*)d_in[2];
    const float* k_w  = (const float*)d_in[3];
    const float* k_b  = (const float*)d_in[4];
    const float* v_w  = (const float*)d_in[5];
    const float* v_b  = (const float*)d_in[6];
    const float* o_w  = (const float*)d_in[7];
    const float* o_b  = (const float*)d_in[8];
    const float* nqw  = (const float*)d_in[9];
    const float* nkw  = (const float*)d_in[10];
    const float* cosT = (const float*)d_in[11];
    const float* sinT = (const float*)d_in[12];
    float* out = (float*)d_out;

    float *dq, *dk, *dv, *dao;
    cudaGetSymbolAddress((void**)&dq, g_q);
    cudaGetSymbolAddress((void**)&dk, g_k);
    cudaGetSymbolAddress((void**)&dv, g_v);
    cudaGetSymbolAddress((void**)&dao, g_ao);

    dim3 gGemm(DIMC / 128, (SEQ + 127) / 128);
    gemm_tf32<<<gGemm, 256>>>(x, q_w, q_b, dq, SEQ);
    gemm_tf32<<<gGemm, 256>>>(x, k_w, k_b, dk, SEQ);
    gemm_tf32<<<gGemm, 256>>>(x, v_w, v_b, dv, SEQ);

    norm_rope_kernel<<<dim3(SEQ, 2), 256>>>(nqw, nkw, cosT, sinT);

    const int smem = ASM_TOT * 4;
    cudaFuncSetAttribute(attn_mma,
                         cudaFuncAttributeMaxDynamicSharedMemorySize, smem);
    attn_mma<<<dim3((SEQ + 63) / 64, NHEAD), 128, smem>>>();

    gemm_tf32<<<gGemm, 256>>>(dao, o_w, o_b, out, SEQ);
}

// round 3
// speedup vs baseline: 3.3933x; 1.4892x over previous
#include <cuda_runtime.h>
#include <math.h>
#include <stdint.h>

#define DIMC 1536
#define NHEAD 12
#define HDIM 128
#define SEQ 5400
#define GHW 900
#define GWID 30

// scratch (device globals: no allocations allowed)
__device__ float g_q[SEQ * DIMC];
__device__ float g_k[SEQ * DIMC];
__device__ float g_v[SEQ * DIMC];
__device__ float g_ao[SEQ * DIMC];
__device__ float g_x[SEQ * DIMC];
__device__ float g_w[4][DIMC * DIMC];

// ---------------------------------------------------------------------------
// helpers
// ---------------------------------------------------------------------------
__device__ __forceinline__ float to_tf32(float x) {
    uint32_t u;
    asm("cvt.rna.tf32.f32 %0, %1;" : "=r"(u) : "f"(x));
    return __uint_as_float(u);
}
__device__ __forceinline__ uint32_t fu(float x) { return __float_as_uint(x); }

__device__ __forceinline__ void mma_tf32(float* c, const uint32_t* a,
                                         uint32_t b0, uint32_t b1) {
    asm volatile(
        "mma.sync.aligned.m16n8k8.row.col.f32.tf32.tf32.f32 "
        "{%0,%1,%2,%3}, {%4,%5,%6,%7}, {%8,%9}, {%0,%1,%2,%3};\n"
        : "+f"(c[0]), "+f"(c[1]), "+f"(c[2]), "+f"(c[3])
        : "r"(a[0]), "r"(a[1]), "r"(a[2]), "r"(a[3]), "r"(b0), "r"(b1));
}

__device__ __forceinline__ void cp16(uint32_t dst, const void* src) {
    asm volatile("cp.async.cg.shared.global [%0], [%1], 16;\n"
                 :: "r"(dst), "l"(src));
}
__device__ __forceinline__ void cp_commit() {
    asm volatile("cp.async.commit_group;\n");
}
template <int N> __device__ __forceinline__ void cp_wait() {
    asm volatile("cp.async.wait_group %0;\n" :: "n"(N));
}

// ---------------------------------------------------------------------------
// elementwise tf32 rounding copy
// ---------------------------------------------------------------------------
__global__ void __launch_bounds__(256) round_copy(
    const float4* __restrict__ s, float4* __restrict__ d, int n4)
{
    int i = blockIdx.x * 256 + threadIdx.x;
    if (i < n4) {
        float4 v = s[i];
        v.x = to_tf32(v.x); v.y = to_tf32(v.y);
        v.z = to_tf32(v.z); v.w = to_tf32(v.w);
        d[i] = v;
    }
}

// ---------------------------------------------------------------------------
// TF32 GEMM: C[M,1536] = A[M,1536] @ B[1536,1536]^T + bias
// A, B pre-rounded to tf32. 128x128 tile, BK=16, 2-stage cp.async pipeline.
// 256 threads (8 warps 2x4), warp tile 64x32.
// ---------------------------------------------------------------------------
#define GSTR 20

template <bool ROUND>
__global__ void __launch_bounds__(256) gemm_tf32(
    const float* __restrict__ A, const float* __restrict__ B,
    const float* __restrict__ bias, float* __restrict__ C, int M)
{
    __shared__ float sA[2][128 * GSTR];
    __shared__ float sB[2][128 * GSTR];
    const int tid = threadIdx.x;
    const int lane = tid & 31;
    const int wid = tid >> 5;
    const int gid = lane >> 2;
    const int tig = lane & 3;
    const int wm = wid & 1;
    const int wn = wid >> 1;
    const int bm = blockIdx.y * 128;
    const int bn = blockIdx.x * 128;
    const uint32_t aAddr = (uint32_t)__cvta_generic_to_shared(&sA[0][0]);
    const uint32_t bAddr = (uint32_t)__cvta_generic_to_shared(&sB[0][0]);

    float acc[4][4][4];
#pragma unroll
    for (int mt = 0; mt < 4; ++mt)
#pragma unroll
        for (int nt = 0; nt < 4; ++nt)
#pragma unroll
            for (int i = 0; i < 4; ++i) acc[mt][nt][i] = 0.f;

    // prefetch tile 0
#pragma unroll
    for (int i = 0; i < 2; ++i) {
        int c = tid + i * 256;
        int r = c >> 2, col = c & 3;
        int ra = bm + r; if (ra > M - 1) ra = M - 1;
        cp16(aAddr + (r * GSTR + col * 4) * 4, A + (size_t)ra * DIMC + col * 4);
        cp16(bAddr + (r * GSTR + col * 4) * 4, B + (size_t)(bn + r) * DIMC + col * 4);
    }
    cp_commit();

    const int NIT = DIMC / 16;  // 96
    for (int ki = 0; ki < NIT; ++ki) {
        const int buf = ki & 1;
        if (ki + 1 < NIT) {
            const int k0 = (ki + 1) * 16;
            const int nb = (ki + 1) & 1;
#pragma unroll
            for (int i = 0; i < 2; ++i) {
                int c = tid + i * 256;
                int r = c >> 2, col = c & 3;
                int ra = bm + r; if (ra > M - 1) ra = M - 1;
                cp16(aAddr + (nb * 128 * GSTR + r * GSTR + col * 4) * 4,
                     A + (size_t)ra * DIMC + k0 + col * 4);
                cp16(bAddr + (nb * 128 * GSTR + r * GSTR + col * 4) * 4,
                     B + (size_t)(bn + r) * DIMC + k0 + col * 4);
            }
            cp_commit();
            cp_wait<1>();
        } else {
            cp_wait<0>();
        }
        __syncthreads();

        const float* pA = &sA[buf][0];
        const float* pB = &sB[buf][0];
#pragma unroll
        for (int ks = 0; ks < 2; ++ks) {
            uint32_t af[4][4], bf[4][2];
#pragma unroll
            for (int mt = 0; mt < 4; ++mt) {
                int base = (wm * 64 + mt * 16 + gid) * GSTR + tig + ks * 8;
                af[mt][0] = fu(pA[base]);
                af[mt][1] = fu(pA[base + 8 * GSTR]);
                af[mt][2] = fu(pA[base + 4]);
                af[mt][3] = fu(pA[base + 8 * GSTR + 4]);
            }
#pragma unroll
            for (int nt = 0; nt < 4; ++nt) {
                int base = (wn * 32 + nt * 8 + gid) * GSTR + tig + ks * 8;
                bf[nt][0] = fu(pB[base]);
                bf[nt][1] = fu(pB[base + 4]);
            }
#pragma unroll
            for (int mt = 0; mt < 4; ++mt)
#pragma unroll
                for (int nt = 0; nt < 4; ++nt)
                    mma_tf32(acc[mt][nt], af[mt], bf[nt][0], bf[nt][1]);
        }
        __syncthreads();
    }

#pragma unroll
    for (int mt = 0; mt < 4; ++mt) {
        int r0 = bm + wm * 64 + mt * 16 + gid;
        int r1 = r0 + 8;
#pragma unroll
        for (int nt = 0; nt < 4; ++nt) {
            int col = bn + wn * 32 + nt * 8 + 2 * tig;
            float b0 = bias[col], b1 = bias[col + 1];
            float2 o0 = make_float2(acc[mt][nt][0] + b0, acc[mt][nt][1] + b1);
            float2 o1 = make_float2(acc[mt][nt][2] + b0, acc[mt][nt][3] + b1);
            if (ROUND) {
                o0.x = to_tf32(o0.x); o0.y = to_tf32(o0.y);
                o1.x = to_tf32(o1.x); o1.y = to_tf32(o1.y);
            }
            if (r0 < M) *(float2*)(C + (size_t)r0 * DIMC + col) = o0;
            if (r1 < M) *(float2*)(C + (size_t)r1 * DIMC + col) = o1;
        }
    }
}

// ---------------------------------------------------------------------------
// Fused RMSNorm + RoPE, in-place. Writes tf32-rounded output;
// q additionally pre-scaled by 1/sqrt(HD).
// ---------------------------------------------------------------------------
__global__ void __launch_bounds__(256) norm_rope_kernel(
    const float* __restrict__ nqw, const float* __restrict__ nkw,
    const float* __restrict__ cosT, const float* __restrict__ sinT)
{
    __shared__ float buf[DIMC];
    __shared__ float red[8];
    const int row = blockIdx.x;
    float* base = blockIdx.y ? g_k : g_q;
    const float* w = blockIdx.y ? nkw : nqw;
    const float sc = blockIdx.y ? 1.0f : 0.08838834764831845f;
    const int tid = threadIdx.x;

    float ss = 0.f;
#pragma unroll
    for (int j = tid; j < DIMC; j += 256) {
        float v = base[(size_t)row * DIMC + j];
        buf[j] = v;
        ss += v * v;
    }
#pragma unroll
    for (int o = 16; o; o >>= 1) ss += __shfl_xor_sync(0xffffffffu, ss, o);
    if ((tid & 31) == 0) red[tid >> 5] = ss;
    __syncthreads();
    float tot = 0.f;
#pragma unroll
    for (int i = 0; i < 8; ++i) tot += red[i];
    const float rms = rsqrtf(tot * (1.0f / DIMC) + 1e-6f);
#pragma unroll
    for (int j = tid; j < DIMC; j += 256) buf[j] = buf[j] * rms * w[j];
    __syncthreads();

    const int f = row / GHW;
    const int rem = row - f * GHW;
    const int h = rem / GWID;
    const int ww = rem - h * GWID;
#pragma unroll
    for (int p = tid; p < DIMC / 2; p += 256) {
        int n = p >> 6;
        int i = p & 63;
        int pos = (i < 22) ? f : (i < 43) ? h : ww;
        float c = cosT[pos * 64 + i];
        float s = sinT[pos * 64 + i];
        int idx = n * HDIM + 2 * i;
        float xr = buf[idx], xi = buf[idx + 1];
        base[(size_t)row * DIMC + idx]     = to_tf32((xr * c - xi * s) * sc);
        base[(size_t)row * DIMC + idx + 1] = to_tf32((xr * s + xi * c) * sc);
    }
}

// ---------------------------------------------------------------------------
// Flash attention, TF32 mma. BQ=128 (8 warps x 16 q-rows), BK=64,
// 256 threads, K/V double-buffered via cp.async (natural layouts).
// K stride 132 (banks 4*gid+tig), V stride 136 (banks 8*tig+gid), P stride 68.
// smem floats: K 2*64*132=16896 | V 2*64*136=17408 | P 128*68=8704 -> 43008
// ---------------------------------------------------------------------------
#define KSTR 132
#define VSTR 136
#define PSTR 68
#define SK_OFF 0
#define SV_OFF 16896
#define SP_OFF 34304
#define ATT_SMEM_FLOATS 43008

__global__ void __launch_bounds__(256, 1) attn_mma()
{
    extern __shared__ float sm[];
    float* sK = sm + SK_OFF;
    float* sV = sm + SV_OFF;
    float* sP = sm + SP_OFF;
    const uint32_t sKa = (uint32_t)__cvta_generic_to_shared(sK);
    const uint32_t sVa = (uint32_t)__cvta_generic_to_shared(sV);

    const int tid = threadIdx.x;
    const int lane = tid & 31;
    const int w = tid >> 5;        // 0..7
    const int gid = lane >> 2;
    const int tig = lane & 3;
    const int w16 = w * 16;
    const int q0 = blockIdx.x * 128;
    const int hoff = blockIdx.y * HDIM;

    // ---- stage Q (pre-rounded, pre-scaled) into K region, lift to regs ----
#pragma unroll
    for (int i = 0; i < 16; ++i) {
        int c = tid + i * 256;
        int r = c >> 5, col = c & 31;
        int sr = q0 + r; if (sr > SEQ - 1) sr = SEQ - 1;
        cp16(sKa + (r * KSTR + col * 4) * 4,
             g_q + (size_t)sr * DIMC + hoff + col * 4);
    }
    cp_commit();
    cp_wait<0>();
    __syncthreads();

    uint32_t qa[16][4];
#pragma unroll
    for (int ks = 0; ks < 16; ++ks) {
        int base = (w16 + gid) * KSTR + tig + ks * 8;
        qa[ks][0] = fu(sK[base]);
        qa[ks][1] = fu(sK[base + 8 * KSTR]);
        qa[ks][2] = fu(sK[base + 4]);
        qa[ks][3] = fu(sK[base + 8 * KSTR + 4]);
    }
    __syncthreads();

    float oacc[16][4];
#pragma unroll
    for (int dt = 0; dt < 16; ++dt)
#pragma unroll
        for (int i = 0; i < 4; ++i) oacc[dt][i] = 0.f;
    float m0 = -1e30f, m1 = -1e30f, l0 = 0.f, l1 = 0.f;

    // ---- prefetch tile 0 ----
#pragma unroll
    for (int i = 0; i < 8; ++i) {
        int c = tid + i * 256;
        int r = c >> 5, col = c & 31;
        int sr = r; if (sr > SEQ - 1) sr = SEQ - 1;
        size_t off = (size_t)sr * DIMC + hoff + col * 4;
        cp16(sKa + (r * KSTR + col * 4) * 4, g_k + off);
        cp16(sVa + (r * VSTR + col * 4) * 4, g_v + off);
    }
    cp_commit();

    const int nkt = (SEQ + 63) / 64;   // 85
    for (int kt = 0; kt < nkt; ++kt) {
        const int buf = kt & 1;
        if (kt + 1 < nkt) {
            const int k0n = (kt + 1) * 64;
            const int nb = (kt + 1) & 1;
#pragma unroll
            for (int i = 0; i < 8; ++i) {
                int c = tid + i * 256;
                int r = c >> 5, col = c & 31;
                int sr = k0n + r; if (sr > SEQ - 1) sr = SEQ - 1;
                size_t off = (size_t)sr * DIMC + hoff + col * 4;
                cp16(sKa + ((nb * 64 + r) * KSTR + col * 4) * 4, g_k + off);
                cp16(sVa + ((nb * 64 + r) * VSTR + col * 4) * 4, g_v + off);
            }
            cp_commit();
            cp_wait<1>();
        } else {
            cp_wait<0>();
        }
        __syncthreads();

        const float* kb = sK + buf * 64 * KSTR;
        const float* vb = sV + buf * 64 * VSTR;
        const int k0 = kt * 64;

        // ---- S = Q K^T ----
        float sacc[8][4];
#pragma unroll
        for (int nt = 0; nt < 8; ++nt)
#pragma unroll
            for (int i = 0; i < 4; ++i) sacc[nt][i] = 0.f;

#pragma unroll
        for (int ks = 0; ks < 16; ++ks) {
#pragma unroll
            for (int nt = 0; nt < 8; ++nt) {
                int base = (nt * 8 + gid) * KSTR + tig + ks * 8;
                mma_tf32(sacc[nt], qa[ks], fu(kb[base]), fu(kb[base + 4]));
            }
        }

        // ---- mask tail keys ----
        const int krem = SEQ - k0;
        if (krem < 64) {
#pragma unroll
            for (int nt = 0; nt < 8; ++nt) {
                int c = nt * 8 + 2 * tig;
                if (c >= krem)     { sacc[nt][0] = -1e30f; sacc[nt][2] = -1e30f; }
                if (c + 1 >= krem) { sacc[nt][1] = -1e30f; sacc[nt][3] = -1e30f; }
            }
        }

        // ---- online softmax ----
        float mx0 = -1e30f, mx1 = -1e30f;
#pragma unroll
        for (int nt = 0; nt < 8; ++nt) {
            mx0 = fmaxf(mx0, fmaxf(sacc[nt][0], sacc[nt][1]));
            mx1 = fmaxf(mx1, fmaxf(sacc[nt][2], sacc[nt][3]));
        }
        mx0 = fmaxf(mx0, __shfl_xor_sync(0xffffffffu, mx0, 1));
        mx0 = fmaxf(mx0, __shfl_xor_sync(0xffffffffu, mx0, 2));
        mx1 = fmaxf(mx1, __shfl_xor_sync(0xffffffffu, mx1, 1));
        mx1 = fmaxf(mx1, __shfl_xor_sync(0xffffffffu, mx1, 2));

        float m0n = fmaxf(m0, mx0), m1n = fmaxf(m1, mx1);
        float f0 = __expf(m0 - m0n), f1 = __expf(m1 - m1n);
        float s0 = 0.f, s1 = 0.f;
#pragma unroll
        for (int nt = 0; nt < 8; ++nt) {
            float p0 = __expf(sacc[nt][0] - m0n);
            float p1 = __expf(sacc[nt][1] - m0n);
            float p2 = __expf(sacc[nt][2] - m1n);
            float p3 = __expf(sacc[nt][3] - m1n);
            s0 += p0 + p1; s1 += p2 + p3;
            *(float2*)(sP + (w16 + gid) * PSTR + nt * 8 + 2 * tig) =
                make_float2(to_tf32(p0), to_tf32(p1));
            *(float2*)(sP + (w16 + gid + 8) * PSTR + nt * 8 + 2 * tig) =
                make_float2(to_tf32(p2), to_tf32(p3));
        }
        s0 += __shfl_xor_sync(0xffffffffu, s0, 1);
        s0 += __shfl_xor_sync(0xffffffffu, s0, 2);
        s1 += __shfl_xor_sync(0xffffffffu, s1, 1);
        s1 += __shfl_xor_sync(0xffffffffu, s1, 2);
        l0 = l0 * f0 + s0;
        l1 = l1 * f1 + s1;
        m0 = m0n; m1 = m1n;
#pragma unroll
        for (int dt = 0; dt < 16; ++dt) {
            oacc[dt][0] *= f0; oacc[dt][1] *= f0;
            oacc[dt][2] *= f1; oacc[dt][3] *= f1;
        }
        __syncwarp();

        // ---- O += P V ----
#pragma unroll
        for (int ks = 0; ks < 8; ++ks) {
            uint32_t pa[4];
            int pb = (w16 + gid) * PSTR + tig + ks * 8;
            pa[0] = fu(sP[pb]);
            pa[1] = fu(sP[pb + 8 * PSTR]);
            pa[2] = fu(sP[pb + 4]);
            pa[3] = fu(sP[pb + 8 * PSTR + 4]);
#pragma unroll
            for (int dt = 0; dt < 16; ++dt) {
                int vbse = (ks * 8 + tig) * VSTR + dt * 8 + gid;
                mma_tf32(oacc[dt], pa, fu(vb[vbse]), fu(vb[vbse + 4 * VSTR]));
            }
        }
        __syncthreads();
    }

    // ---- epilogue: normalize, round to tf32 (feeds O-projection), store ----
    float inv0 = 1.f / l0, inv1 = 1.f / l1;
    int r0 = q0 + w16 + gid;
    int r1 = r0 + 8;
#pragma unroll
    for (int dt = 0; dt < 16; ++dt) {
        int col = dt * 8 + 2 * tig;
        if (r0 < SEQ)
            *(float2*)(g_ao + (size_t)r0 * DIMC + hoff + col) =
                make_float2(to_tf32(oacc[dt][0] * inv0), to_tf32(oacc[dt][1] * inv0));
        if (r1 < SEQ)
            *(float2*)(g_ao + (size_t)r1 * DIMC + hoff + col) =
                make_float2(to_tf32(oacc[dt][2] * inv1), to_tf32(oacc[dt][3] * inv1));
    }
}

// ---------------------------------------------------------------------------
extern "C" void kernel_launch(void* const* d_in, const int* in_sizes, int n_in,
                              void* d_out, int out_size)
{
    const float* x    = (const float*)d_in[0];
    const float* q_w  = (const float*)d_in[1];
    const float* q_b  = (const float*)d_in[2];
    const float* k_w  = (const float*)d_in[3];
    const float* k_b  = (const float*)d_in[4];
    const float* v_w  = (const float*)d_in[5];
    const float* v_b  = (const float*)d_in[6];
    const float* o_w  = (const float*)d_in[7];
    const float* o_b  = (const float*)d_in[8];
    const float* nqw  = (const float*)d_in[9];
    const float* nkw  = (const float*)d_in[10];
    const float* cosT = (const float*)d_in[11];
    const float* sinT = (const float*)d_in[12];
    float* out = (float*)d_out;

    float *dq, *dk, *dv, *dao, *dx, *dw;
    cudaGetSymbolAddress((void**)&dq, g_q);
    cudaGetSymbolAddress((void**)&dk, g_k);
    cudaGetSymbolAddress((void**)&dv, g_v);
    cudaGetSymbolAddress((void**)&dao, g_ao);
    cudaGetSymbolAddress((void**)&dx, g_x);
    cudaGetSymbolAddress((void**)&dw, g_w);

    // pre-round operands to tf32
    const int nx4 = SEQ * DIMC / 4;
    const int nw4 = DIMC * DIMC / 4;
    round_copy<<<(nx4 + 255) / 256, 256>>>((const float4*)x, (float4*)dx, nx4);
    round_copy<<<(nw4 + 255) / 256, 256>>>((const float4*)q_w, (float4*)(dw + 0 * (size_t)DIMC * DIMC), nw4);
    round_copy<<<(nw4 + 255) / 256, 256>>>((const float4*)k_w, (float4*)(dw + 1 * (size_t)DIMC * DIMC), nw4);
    round_copy<<<(nw4 + 255) / 256, 256>>>((const float4*)v_w, (float4*)(dw + 2 * (size_t)DIMC * DIMC), nw4);
    round_copy<<<(nw4 + 255) / 256, 256>>>((const float4*)o_w, (float4*)(dw + 3 * (size_t)DIMC * DIMC), nw4);

    dim3 gGemm(DIMC / 128, (SEQ + 127) / 128);
    gemm_tf32<false><<<gGemm, 256>>>(dx, dw + 0 * (size_t)DIMC * DIMC, q_b, dq, SEQ);
    gemm_tf32<false><<<gGemm, 256>>>(dx, dw + 1 * (size_t)DIMC * DIMC, k_b, dk, SEQ);
    gemm_tf32<true ><<<gGemm, 256>>>(dx, dw + 2 * (size_t)DIMC * DIMC, v_b, dv, SEQ);

    norm_rope_kernel<<<dim3(SEQ, 2), 256>>>(nqw, nkw, cosT, sinT);

    const int smem = ATT_SMEM_FLOATS * 4;
    cudaFuncSetAttribute(attn_mma,
                         cudaFuncAttributeMaxDynamicSharedMemorySize, smem);
    attn_mma<<<dim3((SEQ + 127) / 128, NHEAD), 256, smem>>>();

    gemm_tf32<false><<<gGemm, 256>>>(dao, dw + 3 * (size_t)DIMC * DIMC, o_b, out, SEQ);
}

// round 6
// speedup vs baseline: 6.4111x; 1.8893x over previous
#include <cuda_runtime.h>
#include <cuda_fp16.h>
#include <math.h>
#include <stdint.h>

#define DIMC 1536
#define NHEAD 12
#define HDIM 128
#define SEQ 5400
#define GHW 900
#define GWID 30

// scratch (device globals: no allocations allowed)
__device__ float  g_qf[SEQ * DIMC];
__device__ float  g_kf[SEQ * DIMC];
__device__ __half g_qh[SEQ * DIMC];
__device__ __half g_kh[SEQ * DIMC];
__device__ __half g_vt[NHEAD * HDIM * SEQ + 256];   // [head][d][seq] (+pad)
__device__ __half g_ao[SEQ * DIMC];
__device__ __half g_xh[SEQ * DIMC];
__device__ __half g_wh[4][DIMC * DIMC];

// ---------------------------------------------------------------------------
// helpers
// ---------------------------------------------------------------------------
__device__ __forceinline__ uint32_t packh(float a, float b) {
    __half2 h = __floats2half2_rn(a, b);
    return *(uint32_t*)&h;
}

__device__ __forceinline__ void mma_f16(float* c, const uint32_t* a,
                                        uint32_t b0, uint32_t b1) {
    asm volatile(
        "mma.sync.aligned.m16n8k16.row.col.f32.f16.f16.f32 "
        "{%0,%1,%2,%3}, {%4,%5,%6,%7}, {%8,%9}, {%0,%1,%2,%3};\n"
        : "+f"(c[0]), "+f"(c[1]), "+f"(c[2]), "+f"(c[3])
        : "r"(a[0]), "r"(a[1]), "r"(a[2]), "r"(a[3]), "r"(b0), "r"(b1));
}

__device__ __forceinline__ void cp16(uint32_t dst, const void* src) {
    asm volatile("cp.async.cg.shared.global [%0], [%1], 16;\n"
                 :: "r"(dst), "l"(src));
}
__device__ __forceinline__ void cp_commit() {
    asm volatile("cp.async.commit_group;\n");
}
template <int N> __device__ __forceinline__ void cp_wait() {
    asm volatile("cp.async.wait_group %0;\n" :: "n"(N));
}

// ---------------------------------------------------------------------------
// fp32 -> fp16 conversion copy
// ---------------------------------------------------------------------------
__global__ void __launch_bounds__(256) conv_h(
    const float4* __restrict__ s, __half2* __restrict__ d, int n4)
{
    int i = blockIdx.x * 256 + threadIdx.x;
    if (i < n4) {
        float4 v = s[i];
        d[2 * i + 0] = __floats2half2_rn(v.x, v.y);
        d[2 * i + 1] = __floats2half2_rn(v.z, v.w);
    }
}

// ---------------------------------------------------------------------------
// FP16 GEMM: C[M,1536] = A[M,1536](half) @ B[1536,1536]^T(half) + bias
// 128x128 tile, BK=32, 256 threads (8 warps 2x4), warp tile 64x32.
// MODE 0: fp32 row-major out. MODE 1: half transposed out (g_vt[col][row]).
// ---------------------------------------------------------------------------
#define GSTRH 40     // halves per smem row (32 + 8 pad)

template <int MODE>
__global__ void __launch_bounds__(256) gemm_h(
    const __half* __restrict__ A, const __half* __restrict__ B,
    const float* __restrict__ bias, float* __restrict__ Cf,
    __half* __restrict__ Ct, int M)
{
    __shared__ __half sA[2][128 * GSTRH];
    __shared__ __half sB[2][128 * GSTRH];
    const int tid = threadIdx.x;
    const int lane = tid & 31;
    const int wid = tid >> 5;
    const int gid = lane >> 2;
    const int tig = lane & 3;
    const int wm = wid & 1;
    const int wn = wid >> 1;
    const int bm = blockIdx.y * 128;
    const int bn = blockIdx.x * 128;
    const uint32_t aAddr = (uint32_t)__cvta_generic_to_shared(&sA[0][0]);
    const uint32_t bAddr = (uint32_t)__cvta_generic_to_shared(&sB[0][0]);

    float acc[4][4][4];
#pragma unroll
    for (int mt = 0; mt < 4; ++mt)
#pragma unroll
        for (int nt = 0; nt < 4; ++nt)
#pragma unroll
            for (int i = 0; i < 4; ++i) acc[mt][nt][i] = 0.f;

    auto fill = [&](int buf, int kb) {
        const int k0 = kb * 32;
        const uint32_t ab = aAddr + buf * 128 * GSTRH * 2;
        const uint32_t bb = bAddr + buf * 128 * GSTRH * 2;
#pragma unroll
        for (int i = 0; i < 2; ++i) {
            int c = tid + i * 256;          // 0..511
            int r = c >> 2, c4 = c & 3;
            int ra = bm + r; if (ra > M - 1) ra = M - 1;
            cp16(ab + (r * GSTRH + 8 * c4) * 2,
                 A + (size_t)ra * DIMC + k0 + 8 * c4);
            cp16(bb + (r * GSTRH + 8 * c4) * 2,
                 B + (size_t)(bn + r) * DIMC + k0 + 8 * c4);
        }
        cp_commit();
    };

    fill(0, 0);
    const int NKB = DIMC / 32;   // 48
    for (int kb = 0; kb < NKB; ++kb) {
        const int buf = kb & 1;
        if (kb + 1 < NKB) {
            fill(buf ^ 1, kb + 1);
            cp_wait<1>();
        } else {
            cp_wait<0>();
        }
        __syncthreads();

        const uint32_t* pA = (const uint32_t*)&sA[buf][0];
        const uint32_t* pB = (const uint32_t*)&sB[buf][0];
#pragma unroll
        for (int ks = 0; ks < 2; ++ks) {
            uint32_t af[4][4], bf[4][2];
#pragma unroll
            for (int mt = 0; mt < 4; ++mt) {
                int w0 = (wm * 64 + mt * 16 + gid) * (GSTRH / 2) + ks * 8 + tig;
                af[mt][0] = pA[w0];
                af[mt][1] = pA[w0 + 8 * (GSTRH / 2)];
                af[mt][2] = pA[w0 + 4];
                af[mt][3] = pA[w0 + 8 * (GSTRH / 2) + 4];
            }
#pragma unroll
            for (int nt = 0; nt < 4; ++nt) {
                int w0 = (wn * 32 + nt * 8 + gid) * (GSTRH / 2) + ks * 8 + tig;
                bf[nt][0] = pB[w0];
                bf[nt][1] = pB[w0 + 4];
            }
#pragma unroll
            for (int mt = 0; mt < 4; ++mt)
#pragma unroll
                for (int nt = 0; nt < 4; ++nt)
                    mma_f16(acc[mt][nt], af[mt], bf[nt][0], bf[nt][1]);
        }
        __syncthreads();
    }

#pragma unroll
    for (int mt = 0; mt < 4; ++mt) {
        int r0 = bm + wm * 64 + mt * 16 + gid;
        int r1 = r0 + 8;
#pragma unroll
        for (int nt = 0; nt < 4; ++nt) {
            int col = bn + wn * 32 + nt * 8 + 2 * tig;
            float b0 = __ldg(bias + col), b1 = __ldg(bias + col + 1);
            if (MODE == 0) {
                if (r0 < M)
                    *(float2*)(Cf + (size_t)r0 * DIMC + col) =
                        make_float2(acc[mt][nt][0] + b0, acc[mt][nt][1] + b1);
                if (r1 < M)
                    *(float2*)(Cf + (size_t)r1 * DIMC + col) =
                        make_float2(acc[mt][nt][2] + b0, acc[mt][nt][3] + b1);
            } else {
                // transposed half output: Ct[col * SEQ + row]
                if (r0 < M) {
                    Ct[(size_t)col * SEQ + r0]       = __float2half_rn(acc[mt][nt][0] + b0);
                    Ct[(size_t)(col + 1) * SEQ + r0] = __float2half_rn(acc[mt][nt][1] + b1);
                }
                if (r1 < M) {
                    Ct[(size_t)col * SEQ + r1]       = __float2half_rn(acc[mt][nt][2] + b0);
                    Ct[(size_t)(col + 1) * SEQ + r1] = __float2half_rn(acc[mt][nt][3] + b1);
                }
            }
        }
    }
}

// ---------------------------------------------------------------------------
// Fused RMSNorm + RoPE: reads fp32 q/k projections, writes fp16
// (q pre-scaled by 1/sqrt(HD)).
// ---------------------------------------------------------------------------
__global__ void __launch_bounds__(256) norm_rope_kernel(
    const float* __restrict__ nqw, const float* __restrict__ nkw,
    const float* __restrict__ cosT, const float* __restrict__ sinT)
{
    __shared__ float buf[DIMC];
    __shared__ float red[8];
    const int row = blockIdx.x;
    const float* src = blockIdx.y ? g_kf : g_qf;
    __half* dst = blockIdx.y ? g_kh : g_qh;
    const float* w = blockIdx.y ? nkw : nqw;
    const float sc = blockIdx.y ? 1.0f : 0.08838834764831845f;
    const int tid = threadIdx.x;

    float ss = 0.f;
#pragma unroll
    for (int j = tid; j < DIMC; j += 256) {
        float v = src[(size_t)row * DIMC + j];
        buf[j] = v;
        ss += v * v;
    }
#pragma unroll
    for (int o = 16; o; o >>= 1) ss += __shfl_xor_sync(0xffffffffu, ss, o);
    if ((tid & 31) == 0) red[tid >> 5] = ss;
    __syncthreads();
    float tot = 0.f;
#pragma unroll
    for (int i = 0; i < 8; ++i) tot += red[i];
    const float rms = rsqrtf(tot * (1.0f / DIMC) + 1e-6f);
#pragma unroll
    for (int j = tid; j < DIMC; j += 256) buf[j] = buf[j] * rms * w[j];
    __syncthreads();

    const int f = row / GHW;
    const int rem = row - f * GHW;
    const int h = rem / GWID;
    const int ww = rem - h * GWID;
#pragma unroll
    for (int p = tid; p < DIMC / 2; p += 256) {
        int n = p >> 6;
        int i = p & 63;
        int pos = (i < 22) ? f : (i < 43) ? h : ww;
        float c = cosT[pos * 64 + i];
        float s = sinT[pos * 64 + i];
        int idx = n * HDIM + 2 * i;
        float xr = buf[idx], xi = buf[idx + 1];
        *(__half2*)(dst + (size_t)row * DIMC + idx) =
            __floats2half2_rn((xr * c - xi * s) * sc,
                              (xr * s + xi * c) * sc);
    }
}

// ---------------------------------------------------------------------------
// Flash attention, fp16 mma m16n8k16. BQ=128 (8 warps x 16 q-rows), BK=64,
// 256 threads. K double-buffered [key][d] stride 136; V double-buffered
// transposed [d][key] stride 72 (from g_vt). P kept in registers (C-frag of
// S == A-frag of PV for fp16).
// smem halves: K 2*64*136=17408 | Vt 2*128*72=18432  -> 35840 h = 71680 B
// ---------------------------------------------------------------------------
#define AKSTR 136
#define AVSTR 72
#define AK_W (AKSTR / 2)    // 68 words
#define AV_W (AVSTR / 2)    // 36 words
#define ATT_SMEM_BYTES ((2 * 64 * AKSTR + 2 * 128 * AVSTR) * 2)

__global__ void __launch_bounds__(256, 1) attn_mma()
{
    extern __shared__ __half smh[];
    __half* sK  = smh;
    __half* sVt = smh + 2 * 64 * AKSTR;
    const uint32_t sKa = (uint32_t)__cvta_generic_to_shared(sK);
    const uint32_t sVa = (uint32_t)__cvta_generic_to_shared(sVt);

    const int tid = threadIdx.x;
    const int lane = tid & 31;
    const int w = tid >> 5;        // 0..7
    const int gid = lane >> 2;
    const int tig = lane & 3;
    const int w16 = w * 16;
    const int q0 = blockIdx.x * 128;
    const int head = blockIdx.y;
    const int hoff = head * HDIM;

    // ---- stage Q (fp16, pre-scaled) into K region, lift A-frags to regs ----
#pragma unroll
    for (int i = 0; i < 8; ++i) {
        int c = tid + i * 256;               // 0..2047
        int r = c >> 4, c16 = c & 15;
        int sr = q0 + r; if (sr > SEQ - 1) sr = SEQ - 1;
        cp16(sKa + (r * AKSTR + 8 * c16) * 2,
             g_qh + (size_t)sr * DIMC + hoff + 8 * c16);
    }
    cp_commit();
    cp_wait<0>();
    __syncthreads();

    uint32_t qa[8][4];
    {
        const uint32_t* wQ = (const uint32_t*)sK;
#pragma unroll
        for (int ks = 0; ks < 8; ++ks) {
            int w0 = (w16 + gid) * AK_W + ks * 8 + tig;
            qa[ks][0] = wQ[w0];
            qa[ks][1] = wQ[w0 + 8 * AK_W];
            qa[ks][2] = wQ[w0 + 4];
            qa[ks][3] = wQ[w0 + 8 * AK_W + 4];
        }
    }
    __syncthreads();

    float oacc[16][4];
#pragma unroll
    for (int dt = 0; dt < 16; ++dt)
#pragma unroll
        for (int i = 0; i < 4; ++i) oacc[dt][i] = 0.f;
    float m0 = -1e30f, m1 = -1e30f, l0 = 0.f, l1 = 0.f;

    // ---- fill helper: K [64][128] + Vt [128][64] for one tile ----
    auto fillKV = [&](int buf, int k0) {
#pragma unroll
        for (int i = 0; i < 4; ++i) {
            int c = tid + i * 256;           // 0..1023
            int r = c >> 4, c16 = c & 15;
            int sr = k0 + r; if (sr > SEQ - 1) sr = SEQ - 1;
            cp16(sKa + ((buf * 64 + r) * AKSTR + 8 * c16) * 2,
                 g_kh + (size_t)sr * DIMC + hoff + 8 * c16);
        }
#pragma unroll
        for (int i = 0; i < 4; ++i) {
            int c = tid + i * 256;           // 0..1023
            int r = c >> 3, c8 = c & 7;      // r = d 0..127
            cp16(sVa + ((buf * 128 + r) * AVSTR + 8 * c8) * 2,
                 g_vt + (size_t)(hoff + r) * SEQ + k0 + 8 * c8);
        }
        cp_commit();
    };

    fillKV(0, 0);

    const int nkt = (SEQ + 63) / 64;   // 85
    for (int kt = 0; kt < nkt; ++kt) {
        const int buf = kt & 1;
        if (kt + 1 < nkt) {
            fillKV(buf ^ 1, (kt + 1) * 64);
            cp_wait<1>();
        } else {
            cp_wait<0>();
        }
        __syncthreads();

        const uint32_t* kb = (const uint32_t*)(sK + buf * 64 * AKSTR);
        const uint32_t* vb = (const uint32_t*)(sVt + buf * 128 * AVSTR);
        const int k0 = kt * 64;

        // ---- S = Q K^T ----
        float sacc[8][4];
#pragma unroll
        for (int nt = 0; nt < 8; ++nt)
#pragma unroll
            for (int i = 0; i < 4; ++i) sacc[nt][i] = 0.f;

#pragma unroll
        for (int ks = 0; ks < 8; ++ks) {
#pragma unroll
            for (int nt = 0; nt < 8; ++nt) {
                int w0 = (nt * 8 + gid) * AK_W + ks * 8 + tig;
                mma_f16(sacc[nt], qa[ks], kb[w0], kb[w0 + 4]);
            }
        }

        // ---- mask tail keys ----
        const int krem = SEQ - k0;
        if (krem < 64) {
#pragma unroll
            for (int nt = 0; nt < 8; ++nt) {
                int c = nt * 8 + 2 * tig;
                if (c >= krem)     { sacc[nt][0] = -1e30f; sacc[nt][2] = -1e30f; }
                if (c + 1 >= krem) { sacc[nt][1] = -1e30f; sacc[nt][3] = -1e30f; }
            }
        }

        // ---- online softmax ----
        float mx0 = -1e30f, mx1 = -1e30f;
#pragma unroll
        for (int nt = 0; nt < 8; ++nt) {
            mx0 = fmaxf(mx0, fmaxf(sacc[nt][0], sacc[nt][1]));
            mx1 = fmaxf(mx1, fmaxf(sacc[nt][2], sacc[nt][3]));
        }
        mx0 = fmaxf(mx0, __shfl_xor_sync(0xffffffffu, mx0, 1));
        mx0 = fmaxf(mx0, __shfl_xor_sync(0xffffffffu, mx0, 2));
        mx1 = fmaxf(mx1, __shfl_xor_sync(0xffffffffu, mx1, 1));
        mx1 = fmaxf(mx1, __shfl_xor_sync(0xffffffffu, mx1, 2));

        float m0n = fmaxf(m0, mx0), m1n = fmaxf(m1, mx1);
        float f0 = __expf(m0 - m0n), f1 = __expf(m1 - m1n);
        float s0 = 0.f, s1 = 0.f;
#pragma unroll
        for (int nt = 0; nt < 8; ++nt) {
            sacc[nt][0] = __expf(sacc[nt][0] - m0n);
            sacc[nt][1] = __expf(sacc[nt][1] - m0n);
            sacc[nt][2] = __expf(sacc[nt][2] - m1n);
            sacc[nt][3] = __expf(sacc[nt][3] - m1n);
            s0 += sacc[nt][0] + sacc[nt][1];
            s1 += sacc[nt][2] + sacc[nt][3];
        }
        s0 += __shfl_xor_sync(0xffffffffu, s0, 1);
        s0 += __shfl_xor_sync(0xffffffffu, s0, 2);
        s1 += __shfl_xor_sync(0xffffffffu, s1, 1);
        s1 += __shfl_xor_sync(0xffffffffu, s1, 2);
        l0 = l0 * f0 + s0;
        l1 = l1 * f1 + s1;
        m0 = m0n; m1 = m1n;
#pragma unroll
        for (int dt = 0; dt < 16; ++dt) {
            oacc[dt][0] *= f0; oacc[dt][1] *= f0;
            oacc[dt][2] *= f1; oacc[dt][3] *= f1;
        }

        // ---- pack P (C-frag of S -> A-frag of PV, fp16) ----
        uint32_t ph[4][4];
#pragma unroll
        for (int ks = 0; ks < 4; ++ks) {
            ph[ks][0] = packh(sacc[2 * ks][0],     sacc[2 * ks][1]);
            ph[ks][1] = packh(sacc[2 * ks][2],     sacc[2 * ks][3]);
            ph[ks][2] = packh(sacc[2 * ks + 1][0], sacc[2 * ks + 1][1]);
            ph[ks][3] = packh(sacc[2 * ks + 1][2], sacc[2 * ks + 1][3]);
        }

        // ---- O += P V (V transposed in smem: [d][key]) ----
#pragma unroll
        for (int ks = 0; ks < 4; ++ks) {
#pragma unroll
            for (int dt = 0; dt < 16; ++dt) {
                int w0 = (dt * 8 + gid) * AV_W + ks * 8 + tig;
                mma_f16(oacc[dt], ph[ks], vb[w0], vb[w0 + 4]);
            }
        }
        __syncthreads();
    }

    // ---- epilogue: normalize, convert fp16, store ----
    float inv0 = 1.f / l0, inv1 = 1.f / l1;
    int r0 = q0 + w16 + gid;
    int r1 = r0 + 8;
#pragma unroll
    for (int dt = 0; dt < 16; ++dt) {
        int col = dt * 8 + 2 * tig;
        if (r0 < SEQ)
            *(__half2*)(g_ao + (size_t)r0 * DIMC + hoff + col) =
                __floats2half2_rn(oacc[dt][0] * inv0, oacc[dt][1] * inv0);
        if (r1 < SEQ)
            *(__half2*)(g_ao + (size_t)r1 * DIMC + hoff + col) =
                __floats2half2_rn(oacc[dt][2] * inv1, oacc[dt][3] * inv1);
    }
}

// ---------------------------------------------------------------------------
extern "C" void kernel_launch(void* const* d_in, const int* in_sizes, int n_in,
                              void* d_out, int out_size)
{
    const float* x    = (const float*)d_in[0];
    const float* q_b  = (const float*)d_in[2];
    const float* k_b  = (const float*)d_in[4];
    const float* v_b  = (const float*)d_in[6];
    const float* o_b  = (const float*)d_in[8];
    const float* nqw  = (const float*)d_in[9];
    const float* nkw  = (const float*)d_in[10];
    const float* cosT = (const float*)d_in[11];
    const float* sinT = (const float*)d_in[12];
    float* out = (float*)d_out;

    float *dqf, *dkf;
    __half *dqh, *dkh, *dvt, *dao, *dxh, *dwh;
    cudaGetSymbolAddress((void**)&dqf, g_qf);
    cudaGetSymbolAddress((void**)&dkf, g_kf);
    cudaGetSymbolAddress((void**)&dqh, g_qh);
    cudaGetSymbolAddress((void**)&dkh, g_kh);
    cudaGetSymbolAddress((void**)&dvt, g_vt);
    cudaGetSymbolAddress((void**)&dao, g_ao);
    cudaGetSymbolAddress((void**)&dxh, g_xh);
    cudaGetSymbolAddress((void**)&dwh, g_wh);

    // convert inputs to fp16
    const int nx4 = SEQ * DIMC / 4;
    const int nw4 = DIMC * DIMC / 4;
    conv_h<<<(nx4 + 255) / 256, 256>>>((const float4*)x, (__half2*)dxh, nx4);
    for (int i = 0; i < 4; ++i)
        conv_h<<<(nw4 + 255) / 256, 256>>>(
            (const float4*)d_in[1 + 2 * i],
            (__half2*)(dwh + (size_t)i * DIMC * DIMC), nw4);

    dim3 gGemm(DIMC / 128, (SEQ + 127) / 128);   // 12 x 43
    gemm_h<0><<<gGemm, 256>>>(dxh, dwh + 0 * (size_t)DIMC * DIMC, q_b, dqf, nullptr, SEQ);
    gemm_h<0><<<gGemm, 256>>>(dxh, dwh + 1 * (size_t)DIMC * DIMC, k_b, dkf, nullptr, SEQ);
    gemm_h<1><<<gGemm, 256>>>(dxh, dwh + 2 * (size_t)DIMC * DIMC, v_b, nullptr, dvt, SEQ);

    norm_rope_kernel<<<dim3(SEQ, 2), 256>>>(nqw, nkw, cosT, sinT);

    cudaFuncSetAttribute(attn_mma,
                         cudaFuncAttributeMaxDynamicSharedMemorySize, ATT_SMEM_BYTES);
    attn_mma<<<dim3((SEQ + 127) / 128, NHEAD), 256, ATT_SMEM_BYTES>>>();

    gemm_h<0><<<gGemm, 256>>>(dao, dwh + 3 * (size_t)DIMC * DIMC, o_b, out, nullptr, SEQ);
}

// round 7
// speedup vs baseline: 6.8960x; 1.0756x over previous
#include <cuda_runtime.h>
#include <cuda_fp16.h>
#include <math.h>
#include <stdint.h>

#define DIMC 1536
#define NHEAD 12
#define HDIM 128
#define SEQ 5400
#define GHW 900
#define GWID 30

// scratch (device globals: no allocations allowed)
__device__ float  g_qf[SEQ * DIMC];
__device__ float  g_kf[SEQ * DIMC];
__device__ __half g_qh[SEQ * DIMC];
__device__ __half g_kh[SEQ * DIMC];
__device__ __half g_vt[NHEAD * HDIM * SEQ + 256];   // [head][d][seq] (+pad)
__device__ __half g_ao[SEQ * DIMC];
__device__ __half g_xh[SEQ * DIMC];
__device__ __half g_wh[4][DIMC * DIMC];

// ---------------------------------------------------------------------------
// helpers
// ---------------------------------------------------------------------------
__device__ __forceinline__ uint32_t packh(float a, float b) {
    __half2 h = __floats2half2_rn(a, b);
    return *(uint32_t*)&h;
}

__device__ __forceinline__ void mma_f16(float* c, const uint32_t* a,
                                        uint32_t b0, uint32_t b1) {
    asm volatile(
        "mma.sync.aligned.m16n8k16.row.col.f32.f16.f16.f32 "
        "{%0,%1,%2,%3}, {%4,%5,%6,%7}, {%8,%9}, {%0,%1,%2,%3};\n"
        : "+f"(c[0]), "+f"(c[1]), "+f"(c[2]), "+f"(c[3])
        : "r"(a[0]), "r"(a[1]), "r"(a[2]), "r"(a[3]), "r"(b0), "r"(b1));
}

__device__ __forceinline__ void ldsm4(uint32_t& r0, uint32_t& r1,
                                      uint32_t& r2, uint32_t& r3, uint32_t a) {
    asm volatile("ldmatrix.sync.aligned.m8n8.x4.shared.b16 {%0,%1,%2,%3}, [%4];"
                 : "=r"(r0), "=r"(r1), "=r"(r2), "=r"(r3) : "r"(a));
}

__device__ __forceinline__ void cp16(uint32_t dst, const void* src) {
    asm volatile("cp.async.cg.shared.global [%0], [%1], 16;\n"
                 :: "r"(dst), "l"(src));
}
__device__ __forceinline__ void cp_commit() {
    asm volatile("cp.async.commit_group;\n");
}
template <int N> __device__ __forceinline__ void cp_wait() {
    asm volatile("cp.async.wait_group %0;\n" :: "n"(N));
}

// ---------------------------------------------------------------------------
// fp32 -> fp16 conversion copies
// ---------------------------------------------------------------------------
__global__ void __launch_bounds__(256) conv_h(
    const float4* __restrict__ s, __half2* __restrict__ d, int n4)
{
    int i = blockIdx.x * 256 + threadIdx.x;
    if (i < n4) {
        float4 v = s[i];
        d[2 * i + 0] = __floats2half2_rn(v.x, v.y);
        d[2 * i + 1] = __floats2half2_rn(v.z, v.w);
    }
}

__global__ void __launch_bounds__(256) conv_h4(
    const float4* __restrict__ s0, const float4* __restrict__ s1,
    const float4* __restrict__ s2, const float4* __restrict__ s3,
    __half2* __restrict__ d, int n4)
{
    const float4* s = (blockIdx.y == 0) ? s0 : (blockIdx.y == 1) ? s1
                     : (blockIdx.y == 2) ? s2 : s3;
    __half2* dd = d + (size_t)blockIdx.y * n4 * 2;
    int i = blockIdx.x * 256 + threadIdx.x;
    if (i < n4) {
        float4 v = s[i];
        dd[2 * i + 0] = __floats2half2_rn(v.x, v.y);
        dd[2 * i + 1] = __floats2half2_rn(v.z, v.w);
    }
}

// ---------------------------------------------------------------------------
// FP16 GEMM: C[M,1536] = A[M,1536](half) @ B[1536,1536]^T(half) + bias
// 128x128 tile, BK=32, 256 threads (8 warps 2x4), warp tile 64x32.
// Fragment loads via ldmatrix.x4.
// MODE 0: fp32 row-major out. MODE 1: half transposed out (g_vt[col][row]).
// ---------------------------------------------------------------------------
#define GSTRH 40     // halves per smem row (32 + 8 pad)
#define GBUFB (128 * GSTRH * 2)   // bytes per buffer

template <int MODE>
__global__ void __launch_bounds__(256) gemm_h(
    const __half* __restrict__ A, const __half* __restrict__ B,
    const float* __restrict__ bias, float* __restrict__ Cf,
    __half* __restrict__ Ct, int M)
{
    __shared__ __half sA[2][128 * GSTRH];
    __shared__ __half sB[2][128 * GSTRH];
    const int tid = threadIdx.x;
    const int lane = tid & 31;
    const int wid = tid >> 5;
    const int gid = lane >> 2;
    const int tig = lane & 3;
    const int wm = wid & 1;
    const int wn = wid >> 1;
    const int bm = blockIdx.y * 128;
    const int bn = blockIdx.x * 128;
    const uint32_t aAddr = (uint32_t)__cvta_generic_to_shared(&sA[0][0]);
    const uint32_t bAddr = (uint32_t)__cvta_generic_to_shared(&sB[0][0]);

    // per-lane ldmatrix base offsets (bytes)
    const uint32_t aOff = ((wm * 64 + (lane & 15)) * GSTRH + (lane >> 4) * 8) * 2;
    const uint32_t bOff = ((wn * 32 + (lane & 7) + ((lane >> 4) & 1) * 8) * GSTRH
                           + ((lane >> 3) & 1) * 8) * 2;

    float acc[4][4][4];
#pragma unroll
    for (int mt = 0; mt < 4; ++mt)
#pragma unroll
        for (int nt = 0; nt < 4; ++nt)
#pragma unroll
            for (int i = 0; i < 4; ++i) acc[mt][nt][i] = 0.f;

    auto fill = [&](int buf, int kb) {
        const int k0 = kb * 32;
        const uint32_t ab = aAddr + buf * GBUFB;
        const uint32_t bb = bAddr + buf * GBUFB;
#pragma unroll
        for (int i = 0; i < 2; ++i) {
            int c = tid + i * 256;          // 0..511
            int r = c >> 2, c4 = c & 3;
            int ra = bm + r; if (ra > M - 1) ra = M - 1;
            cp16(ab + (r * GSTRH + 8 * c4) * 2,
                 A + (size_t)ra * DIMC + k0 + 8 * c4);
            cp16(bb + (r * GSTRH + 8 * c4) * 2,
                 B + (size_t)(bn + r) * DIMC + k0 + 8 * c4);
        }
        cp_commit();
    };

    fill(0, 0);
    const int NKB = DIMC / 32;   // 48
    for (int kb = 0; kb < NKB; ++kb) {
        const int buf = kb & 1;
        if (kb + 1 < NKB) {
            fill(buf ^ 1, kb + 1);
            cp_wait<1>();
        } else {
            cp_wait<0>();
        }
        __syncthreads();

        const uint32_t ab = aAddr + buf * GBUFB + aOff;
        const uint32_t bb = bAddr + buf * GBUFB + bOff;
#pragma unroll
        for (int ks = 0; ks < 2; ++ks) {
            uint32_t af[4][4], bf[2][4];
#pragma unroll
            for (int mt = 0; mt < 4; ++mt)
                ldsm4(af[mt][0], af[mt][1], af[mt][2], af[mt][3],
                      ab + (mt * 16 * GSTRH + ks * 16) * 2);
#pragma unroll
            for (int p = 0; p < 2; ++p)
                ldsm4(bf[p][0], bf[p][1], bf[p][2], bf[p][3],
                      bb + (p * 16 * GSTRH + ks * 16) * 2);
#pragma unroll
            for (int mt = 0; mt < 4; ++mt)
#pragma unroll
                for (int p = 0; p < 2; ++p) {
                    mma_f16(acc[mt][2 * p],     af[mt], bf[p][0], bf[p][1]);
                    mma_f16(acc[mt][2 * p + 1], af[mt], bf[p][2], bf[p][3]);
                }
        }
        __syncthreads();
    }

#pragma unroll
    for (int mt = 0; mt < 4; ++mt) {
        int r0 = bm + wm * 64 + mt * 16 + gid;
        int r1 = r0 + 8;
#pragma unroll
        for (int nt = 0; nt < 4; ++nt) {
            int col = bn + wn * 32 + nt * 8 + 2 * tig;
            float b0 = __ldg(bias + col), b1 = __ldg(bias + col + 1);
            if (MODE == 0) {
                if (r0 < M)
                    *(float2*)(Cf + (size_t)r0 * DIMC + col) =
                        make_float2(acc[mt][nt][0] + b0, acc[mt][nt][1] + b1);
                if (r1 < M)
                    *(float2*)(Cf + (size_t)r1 * DIMC + col) =
                        make_float2(acc[mt][nt][2] + b0, acc[mt][nt][3] + b1);
            } else {
                if (r0 < M) {
                    Ct[(size_t)col * SEQ + r0]       = __float2half_rn(acc[mt][nt][0] + b0);
                    Ct[(size_t)(col + 1) * SEQ + r0] = __float2half_rn(acc[mt][nt][1] + b1);
                }
                if (r1 < M) {
                    Ct[(size_t)col * SEQ + r1]       = __float2half_rn(acc[mt][nt][2] + b0);
                    Ct[(size_t)(col + 1) * SEQ + r1] = __float2half_rn(acc[mt][nt][3] + b1);
                }
            }
        }
    }
}

// ---------------------------------------------------------------------------
// Fused RMSNorm + RoPE: reads fp32 q/k projections, writes fp16
// (q pre-scaled by 1/sqrt(HD)).
// ---------------------------------------------------------------------------
__global__ void __launch_bounds__(256) norm_rope_kernel(
    const float* __restrict__ nqw, const float* __restrict__ nkw,
    const float* __restrict__ cosT, const float* __restrict__ sinT)
{
    __shared__ float buf[DIMC];
    __shared__ float red[8];
    const int row = blockIdx.x;
    const float* src = blockIdx.y ? g_kf : g_qf;
    __half* dst = blockIdx.y ? g_kh : g_qh;
    const float* w = blockIdx.y ? nkw : nqw;
    const float sc = blockIdx.y ? 1.0f : 0.08838834764831845f;
    const int tid = threadIdx.x;

    float ss = 0.f;
#pragma unroll
    for (int j = tid; j < DIMC; j += 256) {
        float v = src[(size_t)row * DIMC + j];
        buf[j] = v;
        ss += v * v;
    }
#pragma unroll
    for (int o = 16; o; o >>= 1) ss += __shfl_xor_sync(0xffffffffu, ss, o);
    if ((tid & 31) == 0) red[tid >> 5] = ss;
    __syncthreads();
    float tot = 0.f;
#pragma unroll
    for (int i = 0; i < 8; ++i) tot += red[i];
    const float rms = rsqrtf(tot * (1.0f / DIMC) + 1e-6f);
#pragma unroll
    for (int j = tid; j < DIMC; j += 256) buf[j] = buf[j] * rms * w[j];
    __syncthreads();

    const int f = row / GHW;
    const int rem = row - f * GHW;
    const int h = rem / GWID;
    const int ww = rem - h * GWID;
#pragma unroll
    for (int p = tid; p < DIMC / 2; p += 256) {
        int n = p >> 6;
        int i = p & 63;
        int pos = (i < 22) ? f : (i < 43) ? h : ww;
        float c = cosT[pos * 64 + i];
        float s = sinT[pos * 64 + i];
        int idx = n * HDIM + 2 * i;
        float xr = buf[idx], xi = buf[idx + 1];
        *(__half2*)(dst + (size_t)row * DIMC + idx) =
            __floats2half2_rn((xr * c - xi * s) * sc,
                              (xr * s + xi * c) * sc);
    }
}

// ---------------------------------------------------------------------------
// Flash attention, fp16 mma m16n8k16 + ldmatrix. BQ=128 (8 warps x 16 rows),
// BK=64, 256 threads. K double-buffered [key][d] stride 136; V double-
// buffered transposed [d][key] stride 72. P stays in registers.
// ---------------------------------------------------------------------------
#define AKSTR 136
#define AVSTR 72
#define ATT_SMEM_BYTES ((2 * 64 * AKSTR + 2 * 128 * AVSTR) * 2)

__global__ void __launch_bounds__(256, 1) attn_mma()
{
    extern __shared__ __half smh[];
    __half* sK  = smh;
    __half* sVt = smh + 2 * 64 * AKSTR;
    const uint32_t sKa = (uint32_t)__cvta_generic_to_shared(sK);
    const uint32_t sVa = (uint32_t)__cvta_generic_to_shared(sVt);

    const int tid = threadIdx.x;
    const int lane = tid & 31;
    const int w = tid >> 5;        // 0..7
    const int gid = lane >> 2;
    const int tig = lane & 3;
    const int w16 = w * 16;
    const int q0 = blockIdx.x * 128;
    const int head = blockIdx.y;
    const int hoff = head * HDIM;

    // ldmatrix per-lane base offsets (bytes)
    const uint32_t qOff = ((w16 + (lane & 15)) * AKSTR + (lane >> 4) * 8) * 2;
    const uint32_t kOff = (((lane & 7) + ((lane >> 4) & 1) * 8) * AKSTR
                           + ((lane >> 3) & 1) * 8) * 2;
    const uint32_t vOff = (((lane & 7) + ((lane >> 4) & 1) * 8) * AVSTR
                           + ((lane >> 3) & 1) * 8) * 2;

    // ---- stage Q (fp16, pre-scaled) into K region, lift A-frags to regs ----
#pragma unroll
    for (int i = 0; i < 8; ++i) {
        int c = tid + i * 256;               // 0..2047
        int r = c >> 4, c16 = c & 15;
        int sr = q0 + r; if (sr > SEQ - 1) sr = SEQ - 1;
        cp16(sKa + (r * AKSTR + 8 * c16) * 2,
             g_qh + (size_t)sr * DIMC + hoff + 8 * c16);
    }
    cp_commit();
    cp_wait<0>();
    __syncthreads();

    uint32_t qa[8][4];
#pragma unroll
    for (int ks = 0; ks < 8; ++ks)
        ldsm4(qa[ks][0], qa[ks][1], qa[ks][2], qa[ks][3],
              sKa + qOff + ks * 32);
    __syncthreads();

    float oacc[16][4];
#pragma unroll
    for (int dt = 0; dt < 16; ++dt)
#pragma unroll
        for (int i = 0; i < 4; ++i) oacc[dt][i] = 0.f;
    float m0 = -1e30f, m1 = -1e30f, l0 = 0.f, l1 = 0.f;

    auto fillKV = [&](int buf, int k0) {
#pragma unroll
        for (int i = 0; i < 4; ++i) {
            int c = tid + i * 256;           // 0..1023
            int r = c >> 4, c16 = c & 15;
            int sr = k0 + r; if (sr > SEQ - 1) sr = SEQ - 1;
            cp16(sKa + ((buf * 64 + r) * AKSTR + 8 * c16) * 2,
                 g_kh + (size_t)sr * DIMC + hoff + 8 * c16);
        }
#pragma unroll
        for (int i = 0; i < 4; ++i) {
            int c = tid + i * 256;           // 0..1023
            int r = c >> 3, c8 = c & 7;      // r = d 0..127
            cp16(sVa + ((buf * 128 + r) * AVSTR + 8 * c8) * 2,
                 g_vt + (size_t)(hoff + r) * SEQ + k0 + 8 * c8);
        }
        cp_commit();
    };

    fillKV(0, 0);

    const int nkt = (SEQ + 63) / 64;   // 85
    for (int kt = 0; kt < nkt; ++kt) {
        const int buf = kt & 1;
        if (kt + 1 < nkt) {
            fillKV(buf ^ 1, (kt + 1) * 64);
            cp_wait<1>();
        } else {
            cp_wait<0>();
        }
        __syncthreads();

        const uint32_t kbA = sKa + buf * 64 * AKSTR * 2 + kOff;
        const uint32_t vbA = sVa + buf * 128 * AVSTR * 2 + vOff;
        const int k0 = kt * 64;

        // ---- S = Q K^T ----
        float sacc[8][4];
#pragma unroll
        for (int nt = 0; nt < 8; ++nt)
#pragma unroll
            for (int i = 0; i < 4; ++i) sacc[nt][i] = 0.f;

#pragma unroll
        for (int ks = 0; ks < 8; ++ks) {
#pragma unroll
            for (int p = 0; p < 4; ++p) {
                uint32_t b0, b1, b2, b3;
                ldsm4(b0, b1, b2, b3, kbA + (p * 16 * AKSTR + ks * 16) * 2);
                mma_f16(sacc[2 * p],     qa[ks], b0, b1);
                mma_f16(sacc[2 * p + 1], qa[ks], b2, b3);
            }
        }

        // ---- mask tail keys ----
        const int krem = SEQ - k0;
        if (krem < 64) {
#pragma unroll
            for (int nt = 0; nt < 8; ++nt) {
                int c = nt * 8 + 2 * tig;
                if (c >= krem)     { sacc[nt][0] = -1e30f; sacc[nt][2] = -1e30f; }
                if (c + 1 >= krem) { sacc[nt][1] = -1e30f; sacc[nt][3] = -1e30f; }
            }
        }

        // ---- online softmax ----
        float mx0 = -1e30f, mx1 = -1e30f;
#pragma unroll
        for (int nt = 0; nt < 8; ++nt) {
            mx0 = fmaxf(mx0, fmaxf(sacc[nt][0], sacc[nt][1]));
            mx1 = fmaxf(mx1, fmaxf(sacc[nt][2], sacc[nt][3]));
        }
        mx0 = fmaxf(mx0, __shfl_xor_sync(0xffffffffu, mx0, 1));
        mx0 = fmaxf(mx0, __shfl_xor_sync(0xffffffffu, mx0, 2));
        mx1 = fmaxf(mx1, __shfl_xor_sync(0xffffffffu, mx1, 1));
        mx1 = fmaxf(mx1, __shfl_xor_sync(0xffffffffu, mx1, 2));

        float m0n = fmaxf(m0, mx0), m1n = fmaxf(m1, mx1);
        float f0 = __expf(m0 - m0n), f1 = __expf(m1 - m1n);
        float s0 = 0.f, s1 = 0.f;
#pragma unroll
        for (int nt = 0; nt < 8; ++nt) {
            sacc[nt][0] = __expf(sacc[nt][0] - m0n);
            sacc[nt][1] = __expf(sacc[nt][1] - m0n);
            sacc[nt][2] = __expf(sacc[nt][2] - m1n);
            sacc[nt][3] = __expf(sacc[nt][3] - m1n);
            s0 += sacc[nt][0] + sacc[nt][1];
            s1 += sacc[nt][2] + sacc[nt][3];
        }
        s0 += __shfl_xor_sync(0xffffffffu, s0, 1);
        s0 += __shfl_xor_sync(0xffffffffu, s0, 2);
        s1 += __shfl_xor_sync(0xffffffffu, s1, 1);
        s1 += __shfl_xor_sync(0xffffffffu, s1, 2);
        l0 = l0 * f0 + s0;
        l1 = l1 * f1 + s1;
        m0 = m0n; m1 = m1n;
#pragma unroll
        for (int dt = 0; dt < 16; ++dt) {
            oacc[dt][0] *= f0; oacc[dt][1] *= f0;
            oacc[dt][2] *= f1; oacc[dt][3] *= f1;
        }

        // ---- pack P (C-frag of S -> A-frag of PV, fp16) ----
        uint32_t ph[4][4];
#pragma unroll
        for (int ks = 0; ks < 4; ++ks) {
            ph[ks][0] = packh(sacc[2 * ks][0],     sacc[2 * ks][1]);
            ph[ks][1] = packh(sacc[2 * ks][2],     sacc[2 * ks][3]);
            ph[ks][2] = packh(sacc[2 * ks + 1][0], sacc[2 * ks + 1][1]);
            ph[ks][3] = packh(sacc[2 * ks + 1][2], sacc[2 * ks + 1][3]);
        }

        // ---- O += P V (V transposed in smem: [d][key]) ----
#pragma unroll
        for (int ks = 0; ks < 4; ++ks) {
#pragma unroll
            for (int p = 0; p < 8; ++p) {
                uint32_t v0, v1, v2, v3;
                ldsm4(v0, v1, v2, v3, vbA + (p * 16 * AVSTR + ks * 16) * 2);
                mma_f16(oacc[2 * p],     ph[ks], v0, v1);
                mma_f16(oacc[2 * p + 1], ph[ks], v2, v3);
            }
        }
        __syncthreads();
    }

    // ---- epilogue: normalize, convert fp16, store ----
    float inv0 = 1.f / l0, inv1 = 1.f / l1;
    int r0 = q0 + w16 + gid;
    int r1 = r0 + 8;
#pragma unroll
    for (int dt = 0; dt < 16; ++dt) {
        int col = dt * 8 + 2 * tig;
        if (r0 < SEQ)
            *(__half2*)(g_ao + (size_t)r0 * DIMC + hoff + col) =
                __floats2half2_rn(oacc[dt][0] * inv0, oacc[dt][1] * inv0);
        if (r1 < SEQ)
            *(__half2*)(g_ao + (size_t)r1 * DIMC + hoff + col) =
                __floats2half2_rn(oacc[dt][2] * inv1, oacc[dt][3] * inv1);
    }
}

// ---------------------------------------------------------------------------
extern "C" void kernel_launch(void* const* d_in, const int* in_sizes, int n_in,
                              void* d_out, int out_size)
{
    const float* x    = (const float*)d_in[0];
    const float* q_b  = (const float*)d_in[2];
    const float* k_b  = (const float*)d_in[4];
    const float* v_b  = (const float*)d_in[6];
    const float* o_b  = (const float*)d_in[8];
    const float* nqw  = (const float*)d_in[9];
    const float* nkw  = (const float*)d_in[10];
    const float* cosT = (const float*)d_in[11];
    const float* sinT = (const float*)d_in[12];
    float* out = (float*)d_out;

    float *dqf, *dkf;
    __half *dvt, *dxh, *dwh;
    cudaGetSymbolAddress((void**)&dqf, g_qf);
    cudaGetSymbolAddress((void**)&dkf, g_kf);
    cudaGetSymbolAddress((void**)&dvt, g_vt);
    cudaGetSymbolAddress((void**)&dxh, g_xh);
    cudaGetSymbolAddress((void**)&dwh, g_wh);
    __half* dao;
    cudaGetSymbolAddress((void**)&dao, g_ao);

    // convert inputs to fp16
    const int nx4 = SEQ * DIMC / 4;
    const int nw4 = DIMC * DIMC / 4;
    conv_h<<<(nx4 + 255) / 256, 256>>>((const float4*)x, (__half2*)dxh, nx4);
    conv_h4<<<dim3((nw4 + 255) / 256, 4), 256>>>(
        (const float4*)d_in[1], (const float4*)d_in[3],
        (const float4*)d_in[5], (const float4*)d_in[7],
        (__half2*)dwh, nw4);

    dim3 gGemm(DIMC / 128, (SEQ + 127) / 128);   // 12 x 43
    gemm_h<0><<<gGemm, 256>>>(dxh, dwh + 0 * (size_t)DIMC * DIMC, q_b, dqf, nullptr, SEQ);
    gemm_h<0><<<gGemm, 256>>>(dxh, dwh + 1 * (size_t)DIMC * DIMC, k_b, dkf, nullptr, SEQ);
    gemm_h<1><<<gGemm, 256>>>(dxh, dwh + 2 * (size_t)DIMC * DIMC, v_b, nullptr, dvt, SEQ);

    norm_rope_kernel<<<dim3(SEQ, 2), 256>>>(nqw, nkw, cosT, sinT);

    cudaFuncSetAttribute(attn_mma,
                         cudaFuncAttributeMaxDynamicSharedMemorySize, ATT_SMEM_BYTES);
    attn_mma<<<dim3((SEQ + 127) / 128, NHEAD), 256, ATT_SMEM_BYTES>>>();

    gemm_h<0><<<gGemm, 256>>>(dao, dwh + 3 * (size_t)DIMC * DIMC, o_b, out, nullptr, SEQ);
}